// round 14
// baseline (speedup 1.0000x reference)
#include <cuda_runtime.h>
#include <cuda_fp16.h>
#include <math.h>
#include <stdint.h>

#define B_  4
#define T_  2048
#define D_  1024
#define H_  16
#define DH_ 64
#define FF_ 4096
#define NT  (B_*T_)   // 8192
#define QKVN 3072

// ---------------- scratch ----------------
__device__ __half g_hh  [(size_t)NT*D_];
__device__ __half g_qkv [(size_t)NT*QKVN];
__device__ __half g_ah  [(size_t)NT*D_];
__device__ __half g_fh  [(size_t)NT*FF_];
__device__ float  g_x2  [(size_t)NT*D_];
__device__ __half g_wh  [(size_t)12*1024*1024];
__device__ float  g_bqkv[QKVN];

// ---------------- all-weights fp32 -> fp16 (one launch) ----------------
#define SEG (262144)
__global__ void __launch_bounds__(256) w2h_all(const float* __restrict__ wq,
                                               const float* __restrict__ wk,
                                               const float* __restrict__ wv,
                                               const float* __restrict__ wo,
                                               const float* __restrict__ w1,
                                               const float* __restrict__ w2,
                                               __half* __restrict__ dst)
{
    int i = blockIdx.x * 256 + threadIdx.x;
    if (i >= 12 * SEG) return;
    const float* src;
    int s;
    if      (i <  1 * SEG) { src = wq; s = i; }
    else if (i <  2 * SEG) { src = wk; s = i - 1 * SEG; }
    else if (i <  3 * SEG) { src = wv; s = i - 2 * SEG; }
    else if (i <  4 * SEG) { src = wo; s = i - 3 * SEG; }
    else if (i <  8 * SEG) { src = w1; s = i - 4 * SEG; }
    else                   { src = w2; s = i - 8 * SEG; }
    float4 v = ((const float4*)src)[s];
    __half* d = dst + (size_t)i * 4;
    *(half2*)(d)     = __floats2half2_rn(v.x, v.y);
    *(half2*)(d + 2) = __floats2half2_rn(v.z, v.w);
}

__global__ void __launch_bounds__(256) bpack_k(const float* __restrict__ bq,
                                               const float* __restrict__ bk,
                                               const float* __restrict__ bv,
                                               float* __restrict__ dst)
{
    int i = blockIdx.x * 256 + threadIdx.x;
    if (i < D_) {
        dst[i] = bq[i];
        dst[i + D_] = bk[i];
        dst[i + 2 * D_] = bv[i];
    }
}

// ---------------- LayerNorm: fp32 in, fp16 out ----------------
__global__ void __launch_bounds__(256) ln_k(const float* __restrict__ x,
                                            const float* __restrict__ g,
                                            const float* __restrict__ b,
                                            __half* __restrict__ out)
{
    __shared__ float red[2][8];
    int row = blockIdx.x;
    int tid = threadIdx.x;
    const float* xr = x + (size_t)row * D_;
    int c = tid * 4;
    float4 xv = *(const float4*)(xr + c);
    float s  = xv.x + xv.y + xv.z + xv.w;
    float ss = xv.x*xv.x + xv.y*xv.y + xv.z*xv.z + xv.w*xv.w;
    #pragma unroll
    for (int o = 16; o > 0; o >>= 1) {
        s  += __shfl_down_sync(0xffffffffu, s,  o);
        ss += __shfl_down_sync(0xffffffffu, ss, o);
    }
    if ((tid & 31) == 0) { red[0][tid >> 5] = s; red[1][tid >> 5] = ss; }
    __syncthreads();
    if (tid < 32) {
        s  = (tid < 8) ? red[0][tid] : 0.f;
        ss = (tid < 8) ? red[1][tid] : 0.f;
        #pragma unroll
        for (int o = 4; o > 0; o >>= 1) {
            s  += __shfl_down_sync(0xffffffffu, s,  o);
            ss += __shfl_down_sync(0xffffffffu, ss, o);
        }
        if (tid == 0) { red[0][0] = s; red[1][0] = ss; }
    }
    __syncthreads();
    float mean = red[0][0] * (1.f / D_);
    float var  = red[1][0] * (1.f / D_) - mean * mean;
    float rstd = rsqrtf(var + 1e-5f);
    float4 gv = *(const float4*)(g + c);
    float4 bv = *(const float4*)(b + c);
    float o0 = (xv.x - mean) * rstd * gv.x + bv.x;
    float o1 = (xv.y - mean) * rstd * gv.y + bv.y;
    float o2 = (xv.z - mean) * rstd * gv.z + bv.z;
    float o3 = (xv.w - mean) * rstd * gv.w + bv.w;
    *(half2*)(out + (size_t)row * D_ + c)     = __floats2half2_rn(o0, o1);
    *(half2*)(out + (size_t)row * D_ + c + 2) = __floats2half2_rn(o2, o3);
}

// ---------------- mma / ldmatrix / cp.async helpers ----------------
__device__ __forceinline__ void mma_f16(float4& c,
                                        unsigned a0, unsigned a1, unsigned a2, unsigned a3,
                                        unsigned b0, unsigned b1)
{
    asm volatile("mma.sync.aligned.m16n8k16.row.col.f32.f16.f16.f32 "
                 "{%0,%1,%2,%3}, {%4,%5,%6,%7}, {%8,%9}, {%0,%1,%2,%3};"
                 : "+f"(c.x), "+f"(c.y), "+f"(c.z), "+f"(c.w)
                 : "r"(a0), "r"(a1), "r"(a2), "r"(a3), "r"(b0), "r"(b1));
}
__device__ __forceinline__ void ldsm4(unsigned& r0, unsigned& r1, unsigned& r2, unsigned& r3,
                                      const __half* p)
{
    uint32_t a = (uint32_t)__cvta_generic_to_shared(p);
    asm volatile("ldmatrix.sync.aligned.m8n8.x4.shared.b16 {%0,%1,%2,%3}, [%4];"
                 : "=r"(r0), "=r"(r1), "=r"(r2), "=r"(r3) : "r"(a));
}
__device__ __forceinline__ void ldsm4t(unsigned& r0, unsigned& r1, unsigned& r2, unsigned& r3,
                                       const __half* p)
{
    uint32_t a = (uint32_t)__cvta_generic_to_shared(p);
    asm volatile("ldmatrix.sync.aligned.m8n8.x4.trans.shared.b16 {%0,%1,%2,%3}, [%4];"
                 : "=r"(r0), "=r"(r1), "=r"(r2), "=r"(r3) : "r"(a));
}
__device__ __forceinline__ void cp16(const __half* smem_dst, const __half* gptr) {
    uint32_t a = (uint32_t)__cvta_generic_to_shared(smem_dst);
    asm volatile("cp.async.cg.shared.global [%0], [%1], 16;\n" :: "r"(a), "l"(gptr));
}
__device__ __forceinline__ void cp_commit() { asm volatile("cp.async.commit_group;\n"); }
template<int N>
__device__ __forceinline__ void cp_wait() { asm volatile("cp.async.wait_group %0;\n" :: "n"(N)); }

// ---------------- fp16 GEMM (R12 exact, templated N-tile) ----------------
#define SPADH 40
template<int NBJ, bool GELU, bool RES, bool HOUT>
__global__ void __launch_bounds__(128) hgemm(const __half* __restrict__ A,
                                             const __half* __restrict__ W,
                                             const float* __restrict__ bias,
                                             const float* __restrict__ res,
                                             float* __restrict__ Cf,
                                             __half* __restrict__ Ch,
                                             int M, int N, int K)
{
    constexpr int NROWS = NBJ * 16;
    constexpr int STGH  = (128 + NROWS) * SPADH;

    extern __shared__ __half smg[];

    int tid  = threadIdx.x;
    int warp = tid >> 5;
    int lane = tid & 31;
    int g = lane >> 2;
    int t = lane & 3;
    int wm = (warp >> 1) * 64;
    int wn = (warp & 1) * (NBJ * 8);

    int m0 = blockIdx.y * 128;
    int n0 = blockIdx.x * NROWS;

    int lrow[4], lcb[4];
    #pragma unroll
    for (int u = 0; u < 4; u++) {
        int lin = tid + u * 128;
        lrow[u] = lin >> 2;
        lcb[u]  = (lin & 3) * 8;
    }

    int arow = (lane & 15);
    int acol = 8 * (lane >> 4);
    int brow = (lane & 7) + ((lane >> 4) << 3);
    int bcol = 8 * ((lane >> 3) & 1);

    float4 acc[4][NBJ];
    #pragma unroll
    for (int i = 0; i < 4; i++)
        #pragma unroll
        for (int j = 0; j < NBJ; j++) acc[i][j] = make_float4(0.f, 0.f, 0.f, 0.f);

    #pragma unroll
    for (int st = 0; st < 2; st++) {
        __half* As = smg + st * STGH;
        __half* Bs = As + 128 * SPADH;
        #pragma unroll
        for (int u = 0; u < 4; u++)
            cp16(&As[lrow[u] * SPADH + lcb[u]],
                 A + (size_t)(m0 + lrow[u]) * K + st * 32 + lcb[u]);
        #pragma unroll
        for (int u = 0; u < NBJ / 2; u++) {
            int lin = tid + u * 128;
            int row = lin >> 2;
            int cb  = (lin & 3) * 8;
            cp16(&Bs[row * SPADH + cb],
                 W + (size_t)(n0 + row) * K + st * 32 + cb);
        }
        cp_commit();
    }

    int niter = K >> 5;
    int sidx = 0;
    for (int kt = 0; kt < niter; kt++) {
        cp_wait<1>();
        __syncthreads();
        const __half* Ab = smg + sidx * STGH;
        const __half* Bb = Ab + 128 * SPADH;

        #pragma unroll
        for (int kk = 0; kk < 32; kk += 16) {
            unsigned af[4][4];
            #pragma unroll
            for (int i = 0; i < 4; i++)
                ldsm4(af[i][0], af[i][1], af[i][2], af[i][3],
                      &Ab[(wm + 16 * i + arow) * SPADH + kk + acol]);
            unsigned bf[NBJ][2];
            #pragma unroll
            for (int jj = 0; jj < NBJ / 2; jj++)
                ldsm4(bf[2 * jj][0], bf[2 * jj][1], bf[2 * jj + 1][0], bf[2 * jj + 1][1],
                      &Bb[(wn + 16 * jj + brow) * SPADH + kk + bcol]);
            #pragma unroll
            for (int i = 0; i < 4; i++)
                #pragma unroll
                for (int j = 0; j < NBJ; j++)
                    mma_f16(acc[i][j], af[i][0], af[i][1], af[i][2], af[i][3],
                            bf[j][0], bf[j][1]);
        }

        int j2 = kt + 2;
        if (j2 < niter) {
            int s2 = sidx + 2; if (s2 >= 3) s2 -= 3;
            __half* As = smg + s2 * STGH;
            __half* Bs = As + 128 * SPADH;
            int k0n = j2 * 32;
            #pragma unroll
            for (int u = 0; u < 4; u++)
                cp16(&As[lrow[u] * SPADH + lcb[u]],
                     A + (size_t)(m0 + lrow[u]) * K + k0n + lcb[u]);
            #pragma unroll
            for (int u = 0; u < NBJ / 2; u++) {
                int lin = tid + u * 128;
                int row = lin >> 2;
                int cb  = (lin & 3) * 8;
                cp16(&Bs[row * SPADH + cb],
                     W + (size_t)(n0 + row) * K + k0n + cb);
            }
        }
        cp_commit();
        sidx++; if (sidx == 3) sidx = 0;
    }

    #pragma unroll
    for (int i = 0; i < 4; i++) {
        int r0 = m0 + wm + 16 * i + g;
        int r1 = r0 + 8;
        #pragma unroll
        for (int j = 0; j < NBJ; j++) {
            int col = n0 + wn + 8 * j + 2 * t;
            float b0 = bias[col], b1 = bias[col + 1];
            float v0 = acc[i][j].x + b0;
            float v1 = acc[i][j].y + b1;
            float v2 = acc[i][j].z + b0;
            float v3 = acc[i][j].w + b1;
            if (RES) {
                const float* rp0 = res + (size_t)r0 * N + col;
                const float* rp1 = res + (size_t)r1 * N + col;
                v0 += rp0[0]; v1 += rp0[1]; v2 += rp1[0]; v3 += rp1[1];
            }
            if (GELU) {
                v0 *= normcdff(v0); v1 *= normcdff(v1);
                v2 *= normcdff(v2); v3 *= normcdff(v3);
            }
            if (HOUT) {
                *(half2*)(Ch + (size_t)r0 * N + col) = __floats2half2_rn(v0, v1);
                *(half2*)(Ch + (size_t)r1 * N + col) = __floats2half2_rn(v2, v3);
            } else {
                *(float2*)(Cf + (size_t)r0 * N + col) = make_float2(v0, v1);
                *(float2*)(Cf + (size_t)r1 * N + col) = make_float2(v2, v3);
            }
        }
    }
}

#define GSMEM8 (3 * (128 + 128) * SPADH * (int)sizeof(__half))   // 61,440 B
#define GSMEM4 (3 * (128 + 64)  * SPADH * (int)sizeof(__half))   // 46,080 B

// ---------------- fp16 flash attention: 2-stage cp.async KV pipeline ----------------
// smem: Qs[128][72] + Ps[128][72] + 2 stages of (K 64 rows + V 64 rows)[72] = 73,728 B
// keeps 3 CTAs/SM (unlike the failed 3-stage/92KB attempt).
#define FSP 72
#define FSTG (128 * FSP)                 // halves per KV stage (64 K rows + 64 V rows)
#define FLASH_SMEM ((128 + 128 + 2 * 128) * FSP * (int)sizeof(__half))
__global__ void __launch_bounds__(128) flash_h(const __half* __restrict__ qkv,
                                               __half* __restrict__ o)
{
    extern __shared__ __half smh[];
    __half* Qs  = smh;                    // [128][FSP]
    __half* Ps  = Qs + 128 * FSP;         // [128][FSP]
    __half* KV0 = Ps + 128 * FSP;         // 2 stages

    int tid  = threadIdx.x;
    int warp = tid >> 5;
    int lane = tid & 31;
    int g = lane >> 2;
    int t = lane & 3;

    int bh = blockIdx.y;
    int b  = bh >> 4;
    int h  = bh & 15;
    int qt0 = blockIdx.x * 128;
    size_t qbase = ((size_t)b * T_) * QKVN + (size_t)h * DH_;
    size_t kbase = qbase + D_;
    size_t vbase = qbase + 2 * D_;
    size_t obase = ((size_t)b * T_) * D_ + (size_t)h * DH_;

    int arow = (lane & 15);
    int acol = 8 * (lane >> 4);
    int brow = (lane & 7) + ((lane >> 4) << 3);
    int bcol = 8 * ((lane >> 3) & 1);
    int vrow = (lane & 7) + (((lane >> 3) & 1) << 3);
    int vcol = 8 * (lane >> 4);

    // per-thread KV load coords: 64 rows x 8 chunks per matrix = 512 chunks, 4/thread
    int krow[4], kcb[4];
    #pragma unroll
    for (int u = 0; u < 4; u++) {
        int lin = tid + u * 128;
        krow[u] = lin >> 3;
        kcb[u]  = (lin & 7) * 8;
    }

    // prologue: issue KV tile 0 into stage 0
    {
        __half* Ks = KV0;
        __half* Vs = Ks + 64 * FSP;
        #pragma unroll
        for (int u = 0; u < 4; u++) {
            cp16(&Ks[krow[u] * FSP + kcb[u]],
                 qkv + kbase + (size_t)krow[u] * QKVN + kcb[u]);
            cp16(&Vs[krow[u] * FSP + kcb[u]],
                 qkv + vbase + (size_t)krow[u] * QKVN + kcb[u]);
        }
        cp_commit();
    }

    // load Q (scaled) while KV tile 0 streams
    {
        half2 sc = __float2half2_rn(0.125f);
        #pragma unroll
        for (int it = 0; it < 8; it++) {
            int lin = tid + it * 128;
            int row = lin >> 3;
            int cb  = (lin & 7) * 8;
            uint4 u = *(const uint4*)(qkv + qbase + (size_t)(qt0 + row) * QKVN + cb);
            half2* hp = (half2*)&u;
            hp[0] = __hmul2(hp[0], sc); hp[1] = __hmul2(hp[1], sc);
            hp[2] = __hmul2(hp[2], sc); hp[3] = __hmul2(hp[3], sc);
            *(uint4*)&Qs[row * FSP + cb] = u;
        }
    }
    __syncthreads();

    int r0w = warp * 32;

    unsigned qf[2][4][4];
    #pragma unroll
    for (int mb = 0; mb < 2; mb++)
        #pragma unroll
        for (int ks = 0; ks < 4; ks++)
            ldsm4(qf[mb][ks][0], qf[mb][ks][1], qf[mb][ks][2], qf[mb][ks][3],
                  &Qs[(r0w + 16 * mb + arow) * FSP + ks * 16 + acol]);

    float m_i[4] = {-1e30f, -1e30f, -1e30f, -1e30f};
    float l_i[4] = {0.f, 0.f, 0.f, 0.f};
    float4 oacc[2][8];
    #pragma unroll
    for (int mb = 0; mb < 2; mb++)
        #pragma unroll
        for (int nb = 0; nb < 8; nb++) oacc[mb][nb] = make_float4(0.f, 0.f, 0.f, 0.f);

    int nkt = T_ / 64;   // 32 tiles
    for (int kt = 0; kt < nkt; kt++) {
        cp_wait<0>();        // tile kt resident (only outstanding group)
        __syncthreads();     // also: all warps done reading stage (kt-1)&1

        // issue tile kt+1 into stage (kt+1)&1 (that stage was consumed at kt-1)
        if (kt + 1 < nkt) {
            __half* Ks2 = KV0 + ((kt + 1) & 1) * FSTG;
            __half* Vs2 = Ks2 + 64 * FSP;
            size_t roff = (size_t)(kt + 1) * 64;
            #pragma unroll
            for (int u = 0; u < 4; u++) {
                cp16(&Ks2[krow[u] * FSP + kcb[u]],
                     qkv + kbase + (roff + krow[u]) * QKVN + kcb[u]);
                cp16(&Vs2[krow[u] * FSP + kcb[u]],
                     qkv + vbase + (roff + krow[u]) * QKVN + kcb[u]);
            }
        }
        cp_commit();

        const __half* Ks = KV0 + (kt & 1) * FSTG;
        const __half* Vs = Ks + 64 * FSP;

        float4 sacc[2][8];
        #pragma unroll
        for (int mb = 0; mb < 2; mb++)
            #pragma unroll
            for (int nb = 0; nb < 8; nb++) sacc[mb][nb] = make_float4(0.f, 0.f, 0.f, 0.f);
        #pragma unroll
        for (int ks = 0; ks < 4; ks++) {
            unsigned bb[8][2];
            #pragma unroll
            for (int jj = 0; jj < 4; jj++)
                ldsm4(bb[2 * jj][0], bb[2 * jj][1], bb[2 * jj + 1][0], bb[2 * jj + 1][1],
                      &Ks[(16 * jj + brow) * FSP + ks * 16 + bcol]);
            #pragma unroll
            for (int mb = 0; mb < 2; mb++)
                #pragma unroll
                for (int nb = 0; nb < 8; nb++)
                    mma_f16(sacc[mb][nb], qf[mb][ks][0], qf[mb][ks][1],
                            qf[mb][ks][2], qf[mb][ks][3], bb[nb][0], bb[nb][1]);
        }

        #pragma unroll
        for (int mb = 0; mb < 2; mb++) {
            float mx0 = -1e30f, mx1 = -1e30f;
            #pragma unroll
            for (int nb = 0; nb < 8; nb++) {
                mx0 = fmaxf(mx0, fmaxf(sacc[mb][nb].x, sacc[mb][nb].y));
                mx1 = fmaxf(mx1, fmaxf(sacc[mb][nb].z, sacc[mb][nb].w));
            }
            mx0 = fmaxf(mx0, __shfl_xor_sync(0xffffffffu, mx0, 1));
            mx0 = fmaxf(mx0, __shfl_xor_sync(0xffffffffu, mx0, 2));
            mx1 = fmaxf(mx1, __shfl_xor_sync(0xffffffffu, mx1, 1));
            mx1 = fmaxf(mx1, __shfl_xor_sync(0xffffffffu, mx1, 2));

            float mn0 = fmaxf(m_i[2 * mb + 0], mx0);
            float mn1 = fmaxf(m_i[2 * mb + 1], mx1);
            float al0 = __expf(m_i[2 * mb + 0] - mn0);
            float al1 = __expf(m_i[2 * mb + 1] - mn1);
            m_i[2 * mb + 0] = mn0;
            m_i[2 * mb + 1] = mn1;

            float s0 = 0.f, s1 = 0.f;
            int rbase  = (r0w + mb * 16 + g) * FSP;
            int rbase8 = (r0w + mb * 16 + g + 8) * FSP;
            #pragma unroll
            for (int nb = 0; nb < 8; nb++) {
                float p0 = __expf(sacc[mb][nb].x - mn0);
                float p1 = __expf(sacc[mb][nb].y - mn0);
                float p2 = __expf(sacc[mb][nb].z - mn1);
                float p3 = __expf(sacc[mb][nb].w - mn1);
                s0 += p0 + p1; s1 += p2 + p3;
                int cc = nb * 8 + 2 * t;
                *(half2*)&Ps[rbase + cc]  = __floats2half2_rn(p0, p1);
                *(half2*)&Ps[rbase8 + cc] = __floats2half2_rn(p2, p3);
            }
            s0 += __shfl_xor_sync(0xffffffffu, s0, 1);
            s0 += __shfl_xor_sync(0xffffffffu, s0, 2);
            s1 += __shfl_xor_sync(0xffffffffu, s1, 1);
            s1 += __shfl_xor_sync(0xffffffffu, s1, 2);
            l_i[2 * mb + 0] = l_i[2 * mb + 0] * al0 + s0;
            l_i[2 * mb + 1] = l_i[2 * mb + 1] * al1 + s1;

            #pragma unroll
            for (int nb = 0; nb < 8; nb++) {
                oacc[mb][nb].x *= al0; oacc[mb][nb].y *= al0;
                oacc[mb][nb].z *= al1; oacc[mb][nb].w *= al1;
            }
        }
        __syncwarp();

        #pragma unroll
        for (int ks = 0; ks < 4; ks++) {
            unsigned pf[2][4];
            #pragma unroll
            for (int mb = 0; mb < 2; mb++)
                ldsm4(pf[mb][0], pf[mb][1], pf[mb][2], pf[mb][3],
                      &Ps[(r0w + 16 * mb + arow) * FSP + ks * 16 + acol]);
            unsigned vf[8][2];
            #pragma unroll
            for (int jj = 0; jj < 4; jj++)
                ldsm4t(vf[2 * jj][0], vf[2 * jj][1], vf[2 * jj + 1][0], vf[2 * jj + 1][1],
                       &Vs[(ks * 16 + vrow) * FSP + 16 * jj + vcol]);
            #pragma unroll
            for (int mb = 0; mb < 2; mb++)
                #pragma unroll
                for (int nb = 0; nb < 8; nb++)
                    mma_f16(oacc[mb][nb], pf[mb][0], pf[mb][1], pf[mb][2], pf[mb][3],
                            vf[nb][0], vf[nb][1]);
        }
    }

    #pragma unroll
    for (int mb = 0; mb < 2; mb++) {
        float inv0 = 1.f / l_i[2 * mb + 0];
        float inv1 = 1.f / l_i[2 * mb + 1];
        int row0 = qt0 + r0w + mb * 16 + g;
        int row1 = row0 + 8;
        #pragma unroll
        for (int nb = 0; nb < 8; nb++) {
            int cc = nb * 8 + 2 * t;
            *(half2*)(o + obase + (size_t)row0 * D_ + cc) =
                __floats2half2_rn(oacc[mb][nb].x * inv0, oacc[mb][nb].y * inv0);
            *(half2*)(o + obase + (size_t)row1 * D_ + cc) =
                __floats2half2_rn(oacc[mb][nb].z * inv1, oacc[mb][nb].w * inv1);
        }
    }
}

// ---------------- launch ----------------
extern "C" void kernel_launch(void* const* d_in, const int* in_sizes, int n_in,
                              void* d_out, int out_size)
{
    const float* x    = (const float*)d_in[0];
    const float* ln1g = (const float*)d_in[1];
    const float* ln1b = (const float*)d_in[2];
    const float* ln2g = (const float*)d_in[3];
    const float* ln2b = (const float*)d_in[4];
    const float* wq   = (const float*)d_in[5];
    const float* bq   = (const float*)d_in[6];
    const float* wk   = (const float*)d_in[7];
    const float* bk   = (const float*)d_in[8];
    const float* wv   = (const float*)d_in[9];
    const float* bv   = (const float*)d_in[10];
    const float* wo   = (const float*)d_in[11];
    const float* bo   = (const float*)d_in[12];
    const float* w1   = (const float*)d_in[13];
    const float* b1   = (const float*)d_in[14];
    const float* w2   = (const float*)d_in[15];
    const float* b2   = (const float*)d_in[16];
    float* out = (float*)d_out;

    void* p;
    cudaGetSymbolAddress(&p, g_hh);   __half* h    = (__half*)p;
    cudaGetSymbolAddress(&p, g_qkv);  __half* qkv  = (__half*)p;
    cudaGetSymbolAddress(&p, g_ah);   __half* att  = (__half*)p;
    cudaGetSymbolAddress(&p, g_fh);   __half* ff   = (__half*)p;
    cudaGetSymbolAddress(&p, g_x2);   float*  x2   = (float*)p;
    cudaGetSymbolAddress(&p, g_wh);   __half* wh   = (__half*)p;
    cudaGetSymbolAddress(&p, g_bqkv); float*  bqkv = (float*)p;

    const size_t MB1 = 1024 * 1024;
    __half* hwqkv = wh;
    __half* hwo   = wh + 3 * MB1;
    __half* hw1   = wh + 4 * MB1;
    __half* hw2   = wh + 8 * MB1;

    cudaFuncSetAttribute(flash_h, cudaFuncAttributeMaxDynamicSharedMemorySize, FLASH_SMEM);
    cudaFuncSetAttribute(hgemm<8, false, false, true >, cudaFuncAttributeMaxDynamicSharedMemorySize, GSMEM8);
    cudaFuncSetAttribute(hgemm<8, true,  false, true >, cudaFuncAttributeMaxDynamicSharedMemorySize, GSMEM8);
    cudaFuncSetAttribute(hgemm<4, false, true,  false>, cudaFuncAttributeMaxDynamicSharedMemorySize, GSMEM4);

    w2h_all<<<(12 * SEG + 255) / 256, 256>>>(wq, wk, wv, wo, w1, w2, wh);
    bpack_k<<<(D_ + 255) / 256, 256>>>(bq, bk, bv, bqkv);

    dim3 gQKV(QKVN / 128, NT / 128);   // (24, 64)
    dim3 gD64(D_ / 64, NT / 128);      // (16, 64)
    dim3 gF(FF_ / 128, NT / 128);      // (32, 64)

    ln_k<<<NT, 256>>>(x, ln1g, ln1b, h);
    hgemm<8, false, false, true ><<<gQKV, 128, GSMEM8>>>(h, hwqkv, bqkv, nullptr, nullptr, qkv, NT, QKVN, D_);
    flash_h<<<dim3(T_ / 128, B_ * H_), 128, FLASH_SMEM>>>(qkv, att);
    hgemm<4, false, true,  false><<<gD64, 128, GSMEM4>>>(att, hwo, bo, x, x2, nullptr, NT, D_, D_);
    ln_k<<<NT, 256>>>(x2, ln2g, ln2b, h);
    hgemm<8, true,  false, true ><<<gF, 128, GSMEM8>>>(h, hw1, b1, nullptr, nullptr, ff, NT, FF_, D_);
    hgemm<4, false, true,  false><<<gD64, 128, GSMEM4>>>(ff, hw2, b2, x2, out, nullptr, NT, D_, FF_);
}

// round 15
// speedup vs baseline: 1.0340x; 1.0340x over previous
#include <cuda_runtime.h>
#include <cuda_fp16.h>
#include <math.h>
#include <stdint.h>

#define B_  4
#define T_  2048
#define D_  1024
#define H_  16
#define DH_ 64
#define FF_ 4096
#define NT  (B_*T_)   // 8192
#define QKVN 3072

// ---------------- scratch ----------------
__device__ __half g_hh  [(size_t)NT*D_];
__device__ __half g_qkv [(size_t)NT*QKVN];
__device__ __half g_ah  [(size_t)NT*D_];
__device__ __half g_fh  [(size_t)NT*FF_];
__device__ float  g_x2  [(size_t)NT*D_];
__device__ __half g_wh  [(size_t)12*1024*1024];
__device__ float  g_bqkv[QKVN];

// ---------------- all-weights fp32 -> fp16 (one launch) ----------------
#define SEG (262144)
__global__ void __launch_bounds__(256) w2h_all(const float* __restrict__ wq,
                                               const float* __restrict__ wk,
                                               const float* __restrict__ wv,
                                               const float* __restrict__ wo,
                                               const float* __restrict__ w1,
                                               const float* __restrict__ w2,
                                               __half* __restrict__ dst)
{
    int i = blockIdx.x * 256 + threadIdx.x;
    if (i >= 12 * SEG) return;
    const float* src;
    int s;
    if      (i <  1 * SEG) { src = wq; s = i; }
    else if (i <  2 * SEG) { src = wk; s = i - 1 * SEG; }
    else if (i <  3 * SEG) { src = wv; s = i - 2 * SEG; }
    else if (i <  4 * SEG) { src = wo; s = i - 3 * SEG; }
    else if (i <  8 * SEG) { src = w1; s = i - 4 * SEG; }
    else                   { src = w2; s = i - 8 * SEG; }
    float4 v = ((const float4*)src)[s];
    __half* d = dst + (size_t)i * 4;
    *(half2*)(d)     = __floats2half2_rn(v.x, v.y);
    *(half2*)(d + 2) = __floats2half2_rn(v.z, v.w);
}

__global__ void __launch_bounds__(256) bpack_k(const float* __restrict__ bq,
                                               const float* __restrict__ bk,
                                               const float* __restrict__ bv,
                                               float* __restrict__ dst)
{
    int i = blockIdx.x * 256 + threadIdx.x;
    if (i < D_) {
        dst[i] = bq[i];
        dst[i + D_] = bk[i];
        dst[i + 2 * D_] = bv[i];
    }
}

// ---------------- LayerNorm: fp32 in, fp16 out ----------------
__global__ void __launch_bounds__(256) ln_k(const float* __restrict__ x,
                                            const float* __restrict__ g,
                                            const float* __restrict__ b,
                                            __half* __restrict__ out)
{
    __shared__ float red[2][8];
    int row = blockIdx.x;
    int tid = threadIdx.x;
    const float* xr = x + (size_t)row * D_;
    int c = tid * 4;
    float4 xv = *(const float4*)(xr + c);
    float s  = xv.x + xv.y + xv.z + xv.w;
    float ss = xv.x*xv.x + xv.y*xv.y + xv.z*xv.z + xv.w*xv.w;
    #pragma unroll
    for (int o = 16; o > 0; o >>= 1) {
        s  += __shfl_down_sync(0xffffffffu, s,  o);
        ss += __shfl_down_sync(0xffffffffu, ss, o);
    }
    if ((tid & 31) == 0) { red[0][tid >> 5] = s; red[1][tid >> 5] = ss; }
    __syncthreads();
    if (tid < 32) {
        s  = (tid < 8) ? red[0][tid] : 0.f;
        ss = (tid < 8) ? red[1][tid] : 0.f;
        #pragma unroll
        for (int o = 4; o > 0; o >>= 1) {
            s  += __shfl_down_sync(0xffffffffu, s,  o);
            ss += __shfl_down_sync(0xffffffffu, ss, o);
        }
        if (tid == 0) { red[0][0] = s; red[1][0] = ss; }
    }
    __syncthreads();
    float mean = red[0][0] * (1.f / D_);
    float var  = red[1][0] * (1.f / D_) - mean * mean;
    float rstd = rsqrtf(var + 1e-5f);
    float4 gv = *(const float4*)(g + c);
    float4 bv = *(const float4*)(b + c);
    float o0 = (xv.x - mean) * rstd * gv.x + bv.x;
    float o1 = (xv.y - mean) * rstd * gv.y + bv.y;
    float o2 = (xv.z - mean) * rstd * gv.z + bv.z;
    float o3 = (xv.w - mean) * rstd * gv.w + bv.w;
    *(half2*)(out + (size_t)row * D_ + c)     = __floats2half2_rn(o0, o1);
    *(half2*)(out + (size_t)row * D_ + c + 2) = __floats2half2_rn(o2, o3);
}

// ---------------- mma / ldmatrix / cp.async helpers ----------------
__device__ __forceinline__ void mma_f16(float4& c,
                                        unsigned a0, unsigned a1, unsigned a2, unsigned a3,
                                        unsigned b0, unsigned b1)
{
    asm volatile("mma.sync.aligned.m16n8k16.row.col.f32.f16.f16.f32 "
                 "{%0,%1,%2,%3}, {%4,%5,%6,%7}, {%8,%9}, {%0,%1,%2,%3};"
                 : "+f"(c.x), "+f"(c.y), "+f"(c.z), "+f"(c.w)
                 : "r"(a0), "r"(a1), "r"(a2), "r"(a3), "r"(b0), "r"(b1));
}
__device__ __forceinline__ void ldsm4(unsigned& r0, unsigned& r1, unsigned& r2, unsigned& r3,
                                      const __half* p)
{
    uint32_t a = (uint32_t)__cvta_generic_to_shared(p);
    asm volatile("ldmatrix.sync.aligned.m8n8.x4.shared.b16 {%0,%1,%2,%3}, [%4];"
                 : "=r"(r0), "=r"(r1), "=r"(r2), "=r"(r3) : "r"(a));
}
__device__ __forceinline__ void ldsm4t(unsigned& r0, unsigned& r1, unsigned& r2, unsigned& r3,
                                       const __half* p)
{
    uint32_t a = (uint32_t)__cvta_generic_to_shared(p);
    asm volatile("ldmatrix.sync.aligned.m8n8.x4.trans.shared.b16 {%0,%1,%2,%3}, [%4];"
                 : "=r"(r0), "=r"(r1), "=r"(r2), "=r"(r3) : "r"(a));
}
__device__ __forceinline__ void cp16(const __half* smem_dst, const __half* gptr) {
    uint32_t a = (uint32_t)__cvta_generic_to_shared(smem_dst);
    asm volatile("cp.async.cg.shared.global [%0], [%1], 16;\n" :: "r"(a), "l"(gptr));
}
__device__ __forceinline__ void cp_commit() { asm volatile("cp.async.commit_group;\n"); }
template<int N>
__device__ __forceinline__ void cp_wait() { asm volatile("cp.async.wait_group %0;\n" :: "n"(N)); }

// ---------------- fp16 GEMM (R12 body, templated N-tile) ----------------
#define SPADH 40
template<int NBJ, bool GELU, bool RES, bool HOUT>
__global__ void __launch_bounds__(128) hgemm(const __half* __restrict__ A,
                                             const __half* __restrict__ W,
                                             const float* __restrict__ bias,
                                             const float* __restrict__ res,
                                             float* __restrict__ Cf,
                                             __half* __restrict__ Ch,
                                             int M, int N, int K)
{
    constexpr int NROWS = NBJ * 16;
    constexpr int STGH  = (128 + NROWS) * SPADH;

    extern __shared__ __half smg[];

    int tid  = threadIdx.x;
    int warp = tid >> 5;
    int lane = tid & 31;
    int g = lane >> 2;
    int t = lane & 3;
    int wm = (warp >> 1) * 64;
    int wn = (warp & 1) * (NBJ * 8);

    int m0 = blockIdx.y * 128;
    int n0 = blockIdx.x * NROWS;

    int lrow[4], lcb[4];
    #pragma unroll
    for (int u = 0; u < 4; u++) {
        int lin = tid + u * 128;
        lrow[u] = lin >> 2;
        lcb[u]  = (lin & 3) * 8;
    }

    int arow = (lane & 15);
    int acol = 8 * (lane >> 4);
    int brow = (lane & 7) + ((lane >> 4) << 3);
    int bcol = 8 * ((lane >> 3) & 1);

    float4 acc[4][NBJ];
    #pragma unroll
    for (int i = 0; i < 4; i++)
        #pragma unroll
        for (int j = 0; j < NBJ; j++) acc[i][j] = make_float4(0.f, 0.f, 0.f, 0.f);

    #pragma unroll
    for (int st = 0; st < 2; st++) {
        __half* As = smg + st * STGH;
        __half* Bs = As + 128 * SPADH;
        #pragma unroll
        for (int u = 0; u < 4; u++)
            cp16(&As[lrow[u] * SPADH + lcb[u]],
                 A + (size_t)(m0 + lrow[u]) * K + st * 32 + lcb[u]);
        #pragma unroll
        for (int u = 0; u < NBJ / 2; u++) {
            int lin = tid + u * 128;
            int row = lin >> 2;
            int cb  = (lin & 3) * 8;
            cp16(&Bs[row * SPADH + cb],
                 W + (size_t)(n0 + row) * K + st * 32 + cb);
        }
        cp_commit();
    }

    int niter = K >> 5;
    int sidx = 0;
    for (int kt = 0; kt < niter; kt++) {
        cp_wait<1>();
        __syncthreads();
        const __half* Ab = smg + sidx * STGH;
        const __half* Bb = Ab + 128 * SPADH;

        #pragma unroll
        for (int kk = 0; kk < 32; kk += 16) {
            unsigned af[4][4];
            #pragma unroll
            for (int i = 0; i < 4; i++)
                ldsm4(af[i][0], af[i][1], af[i][2], af[i][3],
                      &Ab[(wm + 16 * i + arow) * SPADH + kk + acol]);
            unsigned bf[NBJ][2];
            #pragma unroll
            for (int jj = 0; jj < NBJ / 2; jj++)
                ldsm4(bf[2 * jj][0], bf[2 * jj][1], bf[2 * jj + 1][0], bf[2 * jj + 1][1],
                      &Bb[(wn + 16 * jj + brow) * SPADH + kk + bcol]);
            #pragma unroll
            for (int i = 0; i < 4; i++)
                #pragma unroll
                for (int j = 0; j < NBJ; j++)
                    mma_f16(acc[i][j], af[i][0], af[i][1], af[i][2], af[i][3],
                            bf[j][0], bf[j][1]);
        }

        int j2 = kt + 2;
        if (j2 < niter) {
            int s2 = sidx + 2; if (s2 >= 3) s2 -= 3;
            __half* As = smg + s2 * STGH;
            __half* Bs = As + 128 * SPADH;
            int k0n = j2 * 32;
            #pragma unroll
            for (int u = 0; u < 4; u++)
                cp16(&As[lrow[u] * SPADH + lcb[u]],
                     A + (size_t)(m0 + lrow[u]) * K + k0n + lcb[u]);
            #pragma unroll
            for (int u = 0; u < NBJ / 2; u++) {
                int lin = tid + u * 128;
                int row = lin >> 2;
                int cb  = (lin & 3) * 8;
                cp16(&Bs[row * SPADH + cb],
                     W + (size_t)(n0 + row) * K + k0n + cb);
            }
        }
        cp_commit();
        sidx++; if (sidx == 3) sidx = 0;
    }

    #pragma unroll
    for (int i = 0; i < 4; i++) {
        int r0 = m0 + wm + 16 * i + g;
        int r1 = r0 + 8;
        #pragma unroll
        for (int j = 0; j < NBJ; j++) {
            int col = n0 + wn + 8 * j + 2 * t;
            float b0 = bias[col], b1 = bias[col + 1];
            float v0 = acc[i][j].x + b0;
            float v1 = acc[i][j].y + b1;
            float v2 = acc[i][j].z + b0;
            float v3 = acc[i][j].w + b1;
            if (RES) {
                const float* rp0 = res + (size_t)r0 * N + col;
                const float* rp1 = res + (size_t)r1 * N + col;
                v0 += rp0[0]; v1 += rp0[1]; v2 += rp1[0]; v3 += rp1[1];
            }
            if (GELU) {
                v0 *= normcdff(v0); v1 *= normcdff(v1);
                v2 *= normcdff(v2); v3 *= normcdff(v3);
            }
            if (HOUT) {
                *(half2*)(Ch + (size_t)r0 * N + col) = __floats2half2_rn(v0, v1);
                *(half2*)(Ch + (size_t)r1 * N + col) = __floats2half2_rn(v2, v3);
            } else {
                *(float2*)(Cf + (size_t)r0 * N + col) = make_float2(v0, v1);
                *(float2*)(Cf + (size_t)r1 * N + col) = make_float2(v2, v3);
            }
        }
    }
}

#define GSMEM4 (3 * (128 + 64) * SPADH * (int)sizeof(__half))   // 46,080 B

// ---------------- fp16 flash attention (R12 exact: sync loads, 64-key tiles) ----------------
#define FSP 72
#define FLASH_SMEM ((128 + 64 + 64 + 128) * FSP * (int)sizeof(__half))
__global__ void __launch_bounds__(128) flash_h(const __half* __restrict__ qkv,
                                               __half* __restrict__ o)
{
    extern __shared__ __half smh[];
    __half* Qs = smh;
    __half* Ks = Qs + 128 * FSP;
    __half* Vs = Ks + 64 * FSP;
    __half* Ps = Vs + 64 * FSP;

    int tid  = threadIdx.x;
    int warp = tid >> 5;
    int lane = tid & 31;
    int g = lane >> 2;
    int t = lane & 3;

    int bh = blockIdx.y;
    int b  = bh >> 4;
    int h  = bh & 15;
    int qt0 = blockIdx.x * 128;
    size_t qbase = ((size_t)b * T_) * QKVN + (size_t)h * DH_;
    size_t kbase = qbase + D_;
    size_t vbase = qbase + 2 * D_;
    size_t obase = ((size_t)b * T_) * D_ + (size_t)h * DH_;

    int arow = (lane & 15);
    int acol = 8 * (lane >> 4);
    int brow = (lane & 7) + ((lane >> 4) << 3);
    int bcol = 8 * ((lane >> 3) & 1);
    int vrow = (lane & 7) + (((lane >> 3) & 1) << 3);
    int vcol = 8 * (lane >> 4);

    {
        half2 sc = __float2half2_rn(0.125f);
        #pragma unroll
        for (int it = 0; it < 8; it++) {
            int lin = tid + it * 128;
            int row = lin >> 3;
            int cb  = (lin & 7) * 8;
            uint4 u = *(const uint4*)(qkv + qbase + (size_t)(qt0 + row) * QKVN + cb);
            half2* hp = (half2*)&u;
            hp[0] = __hmul2(hp[0], sc); hp[1] = __hmul2(hp[1], sc);
            hp[2] = __hmul2(hp[2], sc); hp[3] = __hmul2(hp[3], sc);
            *(uint4*)&Qs[row * FSP + cb] = u;
        }
    }
    __syncthreads();

    int r0w = warp * 32;

    unsigned qf[2][4][4];
    #pragma unroll
    for (int mb = 0; mb < 2; mb++)
        #pragma unroll
        for (int ks = 0; ks < 4; ks++)
            ldsm4(qf[mb][ks][0], qf[mb][ks][1], qf[mb][ks][2], qf[mb][ks][3],
                  &Qs[(r0w + 16 * mb + arow) * FSP + ks * 16 + acol]);

    float m_i[4] = {-1e30f, -1e30f, -1e30f, -1e30f};
    float l_i[4] = {0.f, 0.f, 0.f, 0.f};
    float4 oacc[2][8];
    #pragma unroll
    for (int mb = 0; mb < 2; mb++)
        #pragma unroll
        for (int nb = 0; nb < 8; nb++) oacc[mb][nb] = make_float4(0.f, 0.f, 0.f, 0.f);

    for (int kt0 = 0; kt0 < T_; kt0 += 64) {
        __syncthreads();
        #pragma unroll
        for (int it = 0; it < 4; it++) {
            int lin = tid + it * 128;
            int row = lin >> 3;
            int cb  = (lin & 7) * 8;
            *(uint4*)&Ks[row * FSP + cb] =
                *(const uint4*)(qkv + kbase + (size_t)(kt0 + row) * QKVN + cb);
            *(uint4*)&Vs[row * FSP + cb] =
                *(const uint4*)(qkv + vbase + (size_t)(kt0 + row) * QKVN + cb);
        }
        __syncthreads();

        float4 sacc[2][8];
        #pragma unroll
        for (int mb = 0; mb < 2; mb++)
            #pragma unroll
            for (int nb = 0; nb < 8; nb++) sacc[mb][nb] = make_float4(0.f, 0.f, 0.f, 0.f);
        #pragma unroll
        for (int ks = 0; ks < 4; ks++) {
            unsigned bb[8][2];
            #pragma unroll
            for (int jj = 0; jj < 4; jj++)
                ldsm4(bb[2 * jj][0], bb[2 * jj][1], bb[2 * jj + 1][0], bb[2 * jj + 1][1],
                      &Ks[(16 * jj + brow) * FSP + ks * 16 + bcol]);
            #pragma unroll
            for (int mb = 0; mb < 2; mb++)
                #pragma unroll
                for (int nb = 0; nb < 8; nb++)
                    mma_f16(sacc[mb][nb], qf[mb][ks][0], qf[mb][ks][1],
                            qf[mb][ks][2], qf[mb][ks][3], bb[nb][0], bb[nb][1]);
        }

        #pragma unroll
        for (int mb = 0; mb < 2; mb++) {
            float mx0 = -1e30f, mx1 = -1e30f;
            #pragma unroll
            for (int nb = 0; nb < 8; nb++) {
                mx0 = fmaxf(mx0, fmaxf(sacc[mb][nb].x, sacc[mb][nb].y));
                mx1 = fmaxf(mx1, fmaxf(sacc[mb][nb].z, sacc[mb][nb].w));
            }
            mx0 = fmaxf(mx0, __shfl_xor_sync(0xffffffffu, mx0, 1));
            mx0 = fmaxf(mx0, __shfl_xor_sync(0xffffffffu, mx0, 2));
            mx1 = fmaxf(mx1, __shfl_xor_sync(0xffffffffu, mx1, 1));
            mx1 = fmaxf(mx1, __shfl_xor_sync(0xffffffffu, mx1, 2));

            float mn0 = fmaxf(m_i[2 * mb + 0], mx0);
            float mn1 = fmaxf(m_i[2 * mb + 1], mx1);
            float al0 = __expf(m_i[2 * mb + 0] - mn0);
            float al1 = __expf(m_i[2 * mb + 1] - mn1);
            m_i[2 * mb + 0] = mn0;
            m_i[2 * mb + 1] = mn1;

            float s0 = 0.f, s1 = 0.f;
            int rbase  = (r0w + mb * 16 + g) * FSP;
            int rbase8 = (r0w + mb * 16 + g + 8) * FSP;
            #pragma unroll
            for (int nb = 0; nb < 8; nb++) {
                float p0 = __expf(sacc[mb][nb].x - mn0);
                float p1 = __expf(sacc[mb][nb].y - mn0);
                float p2 = __expf(sacc[mb][nb].z - mn1);
                float p3 = __expf(sacc[mb][nb].w - mn1);
                s0 += p0 + p1; s1 += p2 + p3;
                int cc = nb * 8 + 2 * t;
                *(half2*)&Ps[rbase + cc]  = __floats2half2_rn(p0, p1);
                *(half2*)&Ps[rbase8 + cc] = __floats2half2_rn(p2, p3);
            }
            s0 += __shfl_xor_sync(0xffffffffu, s0, 1);
            s0 += __shfl_xor_sync(0xffffffffu, s0, 2);
            s1 += __shfl_xor_sync(0xffffffffu, s1, 1);
            s1 += __shfl_xor_sync(0xffffffffu, s1, 2);
            l_i[2 * mb + 0] = l_i[2 * mb + 0] * al0 + s0;
            l_i[2 * mb + 1] = l_i[2 * mb + 1] * al1 + s1;

            #pragma unroll
            for (int nb = 0; nb < 8; nb++) {
                oacc[mb][nb].x *= al0; oacc[mb][nb].y *= al0;
                oacc[mb][nb].z *= al1; oacc[mb][nb].w *= al1;
            }
        }
        __syncwarp();

        #pragma unroll
        for (int ks = 0; ks < 4; ks++) {
            unsigned pf[2][4];
            #pragma unroll
            for (int mb = 0; mb < 2; mb++)
                ldsm4(pf[mb][0], pf[mb][1], pf[mb][2], pf[mb][3],
                      &Ps[(r0w + 16 * mb + arow) * FSP + ks * 16 + acol]);
            unsigned vf[8][2];
            #pragma unroll
            for (int jj = 0; jj < 4; jj++)
                ldsm4t(vf[2 * jj][0], vf[2 * jj][1], vf[2 * jj + 1][0], vf[2 * jj + 1][1],
                       &Vs[(ks * 16 + vrow) * FSP + 16 * jj + vcol]);
            #pragma unroll
            for (int mb = 0; mb < 2; mb++)
                #pragma unroll
                for (int nb = 0; nb < 8; nb++)
                    mma_f16(oacc[mb][nb], pf[mb][0], pf[mb][1], pf[mb][2], pf[mb][3],
                            vf[nb][0], vf[nb][1]);
        }
    }

    #pragma unroll
    for (int mb = 0; mb < 2; mb++) {
        float inv0 = 1.f / l_i[2 * mb + 0];
        float inv1 = 1.f / l_i[2 * mb + 1];
        int row0 = qt0 + r0w + mb * 16 + g;
        int row1 = row0 + 8;
        #pragma unroll
        for (int nb = 0; nb < 8; nb++) {
            int cc = nb * 8 + 2 * t;
            *(half2*)(o + obase + (size_t)row0 * D_ + cc) =
                __floats2half2_rn(oacc[mb][nb].x * inv0, oacc[mb][nb].y * inv0);
            *(half2*)(o + obase + (size_t)row1 * D_ + cc) =
                __floats2half2_rn(oacc[mb][nb].z * inv1, oacc[mb][nb].w * inv1);
        }
    }
}

// ---------------- launch ----------------
extern "C" void kernel_launch(void* const* d_in, const int* in_sizes, int n_in,
                              void* d_out, int out_size)
{
    const float* x    = (const float*)d_in[0];
    const float* ln1g = (const float*)d_in[1];
    const float* ln1b = (const float*)d_in[2];
    const float* ln2g = (const float*)d_in[3];
    const float* ln2b = (const float*)d_in[4];
    const float* wq   = (const float*)d_in[5];
    const float* bq   = (const float*)d_in[6];
    const float* wk   = (const float*)d_in[7];
    const float* bk   = (const float*)d_in[8];
    const float* wv   = (const float*)d_in[9];
    const float* bv   = (const float*)d_in[10];
    const float* wo   = (const float*)d_in[11];
    const float* bo   = (const float*)d_in[12];
    const float* w1   = (const float*)d_in[13];
    const float* b1   = (const float*)d_in[14];
    const float* w2   = (const float*)d_in[15];
    const float* b2   = (const float*)d_in[16];
    float* out = (float*)d_out;

    void* p;
    cudaGetSymbolAddress(&p, g_hh);   __half* h    = (__half*)p;
    cudaGetSymbolAddress(&p, g_qkv);  __half* qkv  = (__half*)p;
    cudaGetSymbolAddress(&p, g_ah);   __half* att  = (__half*)p;
    cudaGetSymbolAddress(&p, g_fh);   __half* ff   = (__half*)p;
    cudaGetSymbolAddress(&p, g_x2);   float*  x2   = (float*)p;
    cudaGetSymbolAddress(&p, g_wh);   __half* wh   = (__half*)p;
    cudaGetSymbolAddress(&p, g_bqkv); float*  bqkv = (float*)p;

    const size_t MB1 = 1024 * 1024;
    __half* hwqkv = wh;
    __half* hwo   = wh + 3 * MB1;
    __half* hw1   = wh + 4 * MB1;
    __half* hw2   = wh + 8 * MB1;

    cudaFuncSetAttribute(flash_h, cudaFuncAttributeMaxDynamicSharedMemorySize, FLASH_SMEM);
    cudaFuncSetAttribute(hgemm<4, false, false, true >, cudaFuncAttributeMaxDynamicSharedMemorySize, GSMEM4);
    cudaFuncSetAttribute(hgemm<4, true,  false, true >, cudaFuncAttributeMaxDynamicSharedMemorySize, GSMEM4);
    cudaFuncSetAttribute(hgemm<4, false, true,  false>, cudaFuncAttributeMaxDynamicSharedMemorySize, GSMEM4);

    w2h_all<<<(12 * SEG + 255) / 256, 256>>>(wq, wk, wv, wo, w1, w2, wh);
    bpack_k<<<(D_ + 255) / 256, 256>>>(bq, bk, bv, bqkv);

    dim3 gQKV(QKVN / 64, NT / 128);    // (48, 64) = 3072 CTAs
    dim3 gD64(D_ / 64, NT / 128);      // (16, 64) = 1024 CTAs
    dim3 gF(FF_ / 64, NT / 128);       // (64, 64) = 4096 CTAs

    ln_k<<<NT, 256>>>(x, ln1g, ln1b, h);
    hgemm<4, false, false, true ><<<gQKV, 128, GSMEM4>>>(h, hwqkv, bqkv, nullptr, nullptr, qkv, NT, QKVN, D_);
    flash_h<<<dim3(T_ / 128, B_ * H_), 128, FLASH_SMEM>>>(qkv, att);
    hgemm<4, false, true,  false><<<gD64, 128, GSMEM4>>>(att, hwo, bo, x, x2, nullptr, NT, D_, D_);
    ln_k<<<NT, 256>>>(x2, ln2g, ln2b, h);
    hgemm<4, true,  false, true ><<<gF, 128, GSMEM4>>>(h, hw1, b1, nullptr, nullptr, ff, NT, FF_, D_);
    hgemm<4, false, true,  false><<<gD64, 128, GSMEM4>>>(ff, hw2, b2, x2, out, nullptr, NT, D_, FF_);
}

// round 16
// speedup vs baseline: 1.0491x; 1.0145x over previous
#include <cuda_runtime.h>
#include <cuda_fp16.h>
#include <math.h>
#include <stdint.h>

#define B_  4
#define T_  2048
#define D_  1024
#define H_  16
#define DH_ 64
#define FF_ 4096
#define NT  (B_*T_)   // 8192
#define QKVN 3072

// ---------------- scratch ----------------
__device__ __half g_hh  [(size_t)NT*D_];
__device__ __half g_qkv [(size_t)NT*QKVN];
__device__ __half g_ah  [(size_t)NT*D_];
__device__ __half g_fh  [(size_t)NT*FF_];
__device__ float  g_x2  [(size_t)NT*D_];
__device__ __half g_wh  [(size_t)12*1024*1024];
__device__ float  g_bqkv[QKVN];

// ---------------- all-weights fp32 -> fp16 (one launch) ----------------
#define SEG (262144)
__global__ void __launch_bounds__(256) w2h_all(const float* __restrict__ wq,
                                               const float* __restrict__ wk,
                                               const float* __restrict__ wv,
                                               const float* __restrict__ wo,
                                               const float* __restrict__ w1,
                                               const float* __restrict__ w2,
                                               __half* __restrict__ dst)
{
    int i = blockIdx.x * 256 + threadIdx.x;
    if (i >= 12 * SEG) return;
    const float* src;
    int s;
    if      (i <  1 * SEG) { src = wq; s = i; }
    else if (i <  2 * SEG) { src = wk; s = i - 1 * SEG; }
    else if (i <  3 * SEG) { src = wv; s = i - 2 * SEG; }
    else if (i <  4 * SEG) { src = wo; s = i - 3 * SEG; }
    else if (i <  8 * SEG) { src = w1; s = i - 4 * SEG; }
    else                   { src = w2; s = i - 8 * SEG; }
    float4 v = ((const float4*)src)[s];
    __half* d = dst + (size_t)i * 4;
    *(half2*)(d)     = __floats2half2_rn(v.x, v.y);
    *(half2*)(d + 2) = __floats2half2_rn(v.z, v.w);
}

__global__ void __launch_bounds__(256) bpack_k(const float* __restrict__ bq,
                                               const float* __restrict__ bk,
                                               const float* __restrict__ bv,
                                               float* __restrict__ dst)
{
    int i = blockIdx.x * 256 + threadIdx.x;
    if (i < D_) {
        dst[i] = bq[i];
        dst[i + D_] = bk[i];
        dst[i + 2 * D_] = bv[i];
    }
}

// ---------------- LayerNorm: fp32 in, fp16 out ----------------
__global__ void __launch_bounds__(256) ln_k(const float* __restrict__ x,
                                            const float* __restrict__ g,
                                            const float* __restrict__ b,
                                            __half* __restrict__ out)
{
    __shared__ float red[2][8];
    int row = blockIdx.x;
    int tid = threadIdx.x;
    const float* xr = x + (size_t)row * D_;
    int c = tid * 4;
    float4 xv = *(const float4*)(xr + c);
    float s  = xv.x + xv.y + xv.z + xv.w;
    float ss = xv.x*xv.x + xv.y*xv.y + xv.z*xv.z + xv.w*xv.w;
    #pragma unroll
    for (int o = 16; o > 0; o >>= 1) {
        s  += __shfl_down_sync(0xffffffffu, s,  o);
        ss += __shfl_down_sync(0xffffffffu, ss, o);
    }
    if ((tid & 31) == 0) { red[0][tid >> 5] = s; red[1][tid >> 5] = ss; }
    __syncthreads();
    if (tid < 32) {
        s  = (tid < 8) ? red[0][tid] : 0.f;
        ss = (tid < 8) ? red[1][tid] : 0.f;
        #pragma unroll
        for (int o = 4; o > 0; o >>= 1) {
            s  += __shfl_down_sync(0xffffffffu, s,  o);
            ss += __shfl_down_sync(0xffffffffu, ss, o);
        }
        if (tid == 0) { red[0][0] = s; red[1][0] = ss; }
    }
    __syncthreads();
    float mean = red[0][0] * (1.f / D_);
    float var  = red[1][0] * (1.f / D_) - mean * mean;
    float rstd = rsqrtf(var + 1e-5f);
    float4 gv = *(const float4*)(g + c);
    float4 bv = *(const float4*)(b + c);
    float o0 = (xv.x - mean) * rstd * gv.x + bv.x;
    float o1 = (xv.y - mean) * rstd * gv.y + bv.y;
    float o2 = (xv.z - mean) * rstd * gv.z + bv.z;
    float o3 = (xv.w - mean) * rstd * gv.w + bv.w;
    *(half2*)(out + (size_t)row * D_ + c)     = __floats2half2_rn(o0, o1);
    *(half2*)(out + (size_t)row * D_ + c + 2) = __floats2half2_rn(o2, o3);
}

// ---------------- mma / ldmatrix / cp.async helpers ----------------
__device__ __forceinline__ void mma_f16(float4& c,
                                        unsigned a0, unsigned a1, unsigned a2, unsigned a3,
                                        unsigned b0, unsigned b1)
{
    asm volatile("mma.sync.aligned.m16n8k16.row.col.f32.f16.f16.f32 "
                 "{%0,%1,%2,%3}, {%4,%5,%6,%7}, {%8,%9}, {%0,%1,%2,%3};"
                 : "+f"(c.x), "+f"(c.y), "+f"(c.z), "+f"(c.w)
                 : "r"(a0), "r"(a1), "r"(a2), "r"(a3), "r"(b0), "r"(b1));
}
__device__ __forceinline__ void ldsm4(unsigned& r0, unsigned& r1, unsigned& r2, unsigned& r3,
                                      const __half* p)
{
    uint32_t a = (uint32_t)__cvta_generic_to_shared(p);
    asm volatile("ldmatrix.sync.aligned.m8n8.x4.shared.b16 {%0,%1,%2,%3}, [%4];"
                 : "=r"(r0), "=r"(r1), "=r"(r2), "=r"(r3) : "r"(a));
}
__device__ __forceinline__ void ldsm4t(unsigned& r0, unsigned& r1, unsigned& r2, unsigned& r3,
                                       const __half* p)
{
    uint32_t a = (uint32_t)__cvta_generic_to_shared(p);
    asm volatile("ldmatrix.sync.aligned.m8n8.x4.trans.shared.b16 {%0,%1,%2,%3}, [%4];"
                 : "=r"(r0), "=r"(r1), "=r"(r2), "=r"(r3) : "r"(a));
}
__device__ __forceinline__ void cp16(const __half* smem_dst, const __half* gptr) {
    uint32_t a = (uint32_t)__cvta_generic_to_shared(smem_dst);
    asm volatile("cp.async.cg.shared.global [%0], [%1], 16;\n" :: "r"(a), "l"(gptr));
}
__device__ __forceinline__ void cp_commit() { asm volatile("cp.async.commit_group;\n"); }
template<int N>
__device__ __forceinline__ void cp_wait() { asm volatile("cp.async.wait_group %0;\n" :: "n"(N)); }

// ---------------- fp16 GEMM (templated N-tile; NBJ=8 or 4) ----------------
#define SPADH 40
template<int NBJ, bool GELU, bool RES, bool HOUT>
__global__ void __launch_bounds__(128) hgemm(const __half* __restrict__ A,
                                             const __half* __restrict__ W,
                                             const float* __restrict__ bias,
                                             const float* __restrict__ res,
                                             float* __restrict__ Cf,
                                             __half* __restrict__ Ch,
                                             int M, int N, int K)
{
    constexpr int NROWS = NBJ * 16;
    constexpr int STGH  = (128 + NROWS) * SPADH;

    extern __shared__ __half smg[];

    int tid  = threadIdx.x;
    int warp = tid >> 5;
    int lane = tid & 31;
    int g = lane >> 2;
    int t = lane & 3;
    int wm = (warp >> 1) * 64;
    int wn = (warp & 1) * (NBJ * 8);

    int m0 = blockIdx.y * 128;
    int n0 = blockIdx.x * NROWS;

    int lrow[4], lcb[4];
    #pragma unroll
    for (int u = 0; u < 4; u++) {
        int lin = tid + u * 128;
        lrow[u] = lin >> 2;
        lcb[u]  = (lin & 3) * 8;
    }

    int arow = (lane & 15);
    int acol = 8 * (lane >> 4);
    int brow = (lane & 7) + ((lane >> 4) << 3);
    int bcol = 8 * ((lane >> 3) & 1);

    float4 acc[4][NBJ];
    #pragma unroll
    for (int i = 0; i < 4; i++)
        #pragma unroll
        for (int j = 0; j < NBJ; j++) acc[i][j] = make_float4(0.f, 0.f, 0.f, 0.f);

    #pragma unroll
    for (int st = 0; st < 2; st++) {
        __half* As = smg + st * STGH;
        __half* Bs = As + 128 * SPADH;
        #pragma unroll
        for (int u = 0; u < 4; u++)
            cp16(&As[lrow[u] * SPADH + lcb[u]],
                 A + (size_t)(m0 + lrow[u]) * K + st * 32 + lcb[u]);
        #pragma unroll
        for (int u = 0; u < NBJ / 2; u++) {
            int lin = tid + u * 128;
            int row = lin >> 2;
            int cb  = (lin & 3) * 8;
            cp16(&Bs[row * SPADH + cb],
                 W + (size_t)(n0 + row) * K + st * 32 + cb);
        }
        cp_commit();
    }

    int niter = K >> 5;
    int sidx = 0;
    for (int kt = 0; kt < niter; kt++) {
        cp_wait<1>();
        __syncthreads();
        const __half* Ab = smg + sidx * STGH;
        const __half* Bb = Ab + 128 * SPADH;

        #pragma unroll
        for (int kk = 0; kk < 32; kk += 16) {
            unsigned af[4][4];
            #pragma unroll
            for (int i = 0; i < 4; i++)
                ldsm4(af[i][0], af[i][1], af[i][2], af[i][3],
                      &Ab[(wm + 16 * i + arow) * SPADH + kk + acol]);
            unsigned bf[NBJ][2];
            #pragma unroll
            for (int jj = 0; jj < NBJ / 2; jj++)
                ldsm4(bf[2 * jj][0], bf[2 * jj][1], bf[2 * jj + 1][0], bf[2 * jj + 1][1],
                      &Bb[(wn + 16 * jj + brow) * SPADH + kk + bcol]);
            #pragma unroll
            for (int i = 0; i < 4; i++)
                #pragma unroll
                for (int j = 0; j < NBJ; j++)
                    mma_f16(acc[i][j], af[i][0], af[i][1], af[i][2], af[i][3],
                            bf[j][0], bf[j][1]);
        }

        int j2 = kt + 2;
        if (j2 < niter) {
            int s2 = sidx + 2; if (s2 >= 3) s2 -= 3;
            __half* As = smg + s2 * STGH;
            __half* Bs = As + 128 * SPADH;
            int k0n = j2 * 32;
            #pragma unroll
            for (int u = 0; u < 4; u++)
                cp16(&As[lrow[u] * SPADH + lcb[u]],
                     A + (size_t)(m0 + lrow[u]) * K + k0n + lcb[u]);
            #pragma unroll
            for (int u = 0; u < NBJ / 2; u++) {
                int lin = tid + u * 128;
                int row = lin >> 2;
                int cb  = (lin & 3) * 8;
                cp16(&Bs[row * SPADH + cb],
                     W + (size_t)(n0 + row) * K + k0n + cb);
            }
        }
        cp_commit();
        sidx++; if (sidx == 3) sidx = 0;
    }

    #pragma unroll
    for (int i = 0; i < 4; i++) {
        int r0 = m0 + wm + 16 * i + g;
        int r1 = r0 + 8;
        #pragma unroll
        for (int j = 0; j < NBJ; j++) {
            int col = n0 + wn + 8 * j + 2 * t;
            float b0 = bias[col], b1 = bias[col + 1];
            float v0 = acc[i][j].x + b0;
            float v1 = acc[i][j].y + b1;
            float v2 = acc[i][j].z + b0;
            float v3 = acc[i][j].w + b1;
            if (RES) {
                const float* rp0 = res + (size_t)r0 * N + col;
                const float* rp1 = res + (size_t)r1 * N + col;
                v0 += rp0[0]; v1 += rp0[1]; v2 += rp1[0]; v3 += rp1[1];
            }
            if (GELU) {
                v0 *= normcdff(v0); v1 *= normcdff(v1);
                v2 *= normcdff(v2); v3 *= normcdff(v3);
            }
            if (HOUT) {
                *(half2*)(Ch + (size_t)r0 * N + col) = __floats2half2_rn(v0, v1);
                *(half2*)(Ch + (size_t)r1 * N + col) = __floats2half2_rn(v2, v3);
            } else {
                *(float2*)(Cf + (size_t)r0 * N + col) = make_float2(v0, v1);
                *(float2*)(Cf + (size_t)r1 * N + col) = make_float2(v2, v3);
            }
        }
    }
}

#define GSMEM8 (3 * (128 + 128) * SPADH * (int)sizeof(__half))   // 61,440 B
#define GSMEM4 (3 * (128 + 64)  * SPADH * (int)sizeof(__half))   // 46,080 B

// ---------------- fp16 flash attention (R12 exact: sync loads, 64-key tiles) ----------------
#define FSP 72
#define FLASH_SMEM ((128 + 64 + 64 + 128) * FSP * (int)sizeof(__half))
__global__ void __launch_bounds__(128) flash_h(const __half* __restrict__ qkv,
                                               __half* __restrict__ o)
{
    extern __shared__ __half smh[];
    __half* Qs = smh;
    __half* Ks = Qs + 128 * FSP;
    __half* Vs = Ks + 64 * FSP;
    __half* Ps = Vs + 64 * FSP;

    int tid  = threadIdx.x;
    int warp = tid >> 5;
    int lane = tid & 31;
    int g = lane >> 2;
    int t = lane & 3;

    int bh = blockIdx.y;
    int b  = bh >> 4;
    int h  = bh & 15;
    int qt0 = blockIdx.x * 128;
    size_t qbase = ((size_t)b * T_) * QKVN + (size_t)h * DH_;
    size_t kbase = qbase + D_;
    size_t vbase = qbase + 2 * D_;
    size_t obase = ((size_t)b * T_) * D_ + (size_t)h * DH_;

    int arow = (lane & 15);
    int acol = 8 * (lane >> 4);
    int brow = (lane & 7) + ((lane >> 4) << 3);
    int bcol = 8 * ((lane >> 3) & 1);
    int vrow = (lane & 7) + (((lane >> 3) & 1) << 3);
    int vcol = 8 * (lane >> 4);

    {
        half2 sc = __float2half2_rn(0.125f);
        #pragma unroll
        for (int it = 0; it < 8; it++) {
            int lin = tid + it * 128;
            int row = lin >> 3;
            int cb  = (lin & 7) * 8;
            uint4 u = *(const uint4*)(qkv + qbase + (size_t)(qt0 + row) * QKVN + cb);
            half2* hp = (half2*)&u;
            hp[0] = __hmul2(hp[0], sc); hp[1] = __hmul2(hp[1], sc);
            hp[2] = __hmul2(hp[2], sc); hp[3] = __hmul2(hp[3], sc);
            *(uint4*)&Qs[row * FSP + cb] = u;
        }
    }
    __syncthreads();

    int r0w = warp * 32;

    unsigned qf[2][4][4];
    #pragma unroll
    for (int mb = 0; mb < 2; mb++)
        #pragma unroll
        for (int ks = 0; ks < 4; ks++)
            ldsm4(qf[mb][ks][0], qf[mb][ks][1], qf[mb][ks][2], qf[mb][ks][3],
                  &Qs[(r0w + 16 * mb + arow) * FSP + ks * 16 + acol]);

    float m_i[4] = {-1e30f, -1e30f, -1e30f, -1e30f};
    float l_i[4] = {0.f, 0.f, 0.f, 0.f};
    float4 oacc[2][8];
    #pragma unroll
    for (int mb = 0; mb < 2; mb++)
        #pragma unroll
        for (int nb = 0; nb < 8; nb++) oacc[mb][nb] = make_float4(0.f, 0.f, 0.f, 0.f);

    for (int kt0 = 0; kt0 < T_; kt0 += 64) {
        __syncthreads();
        #pragma unroll
        for (int it = 0; it < 4; it++) {
            int lin = tid + it * 128;
            int row = lin >> 3;
            int cb  = (lin & 7) * 8;
            *(uint4*)&Ks[row * FSP + cb] =
                *(const uint4*)(qkv + kbase + (size_t)(kt0 + row) * QKVN + cb);
            *(uint4*)&Vs[row * FSP + cb] =
                *(const uint4*)(qkv + vbase + (size_t)(kt0 + row) * QKVN + cb);
        }
        __syncthreads();

        float4 sacc[2][8];
        #pragma unroll
        for (int mb = 0; mb < 2; mb++)
            #pragma unroll
            for (int nb = 0; nb < 8; nb++) sacc[mb][nb] = make_float4(0.f, 0.f, 0.f, 0.f);
        #pragma unroll
        for (int ks = 0; ks < 4; ks++) {
            unsigned bb[8][2];
            #pragma unroll
            for (int jj = 0; jj < 4; jj++)
                ldsm4(bb[2 * jj][0], bb[2 * jj][1], bb[2 * jj + 1][0], bb[2 * jj + 1][1],
                      &Ks[(16 * jj + brow) * FSP + ks * 16 + bcol]);
            #pragma unroll
            for (int mb = 0; mb < 2; mb++)
                #pragma unroll
                for (int nb = 0; nb < 8; nb++)
                    mma_f16(sacc[mb][nb], qf[mb][ks][0], qf[mb][ks][1],
                            qf[mb][ks][2], qf[mb][ks][3], bb[nb][0], bb[nb][1]);
        }

        #pragma unroll
        for (int mb = 0; mb < 2; mb++) {
            float mx0 = -1e30f, mx1 = -1e30f;
            #pragma unroll
            for (int nb = 0; nb < 8; nb++) {
                mx0 = fmaxf(mx0, fmaxf(sacc[mb][nb].x, sacc[mb][nb].y));
                mx1 = fmaxf(mx1, fmaxf(sacc[mb][nb].z, sacc[mb][nb].w));
            }
            mx0 = fmaxf(mx0, __shfl_xor_sync(0xffffffffu, mx0, 1));
            mx0 = fmaxf(mx0, __shfl_xor_sync(0xffffffffu, mx0, 2));
            mx1 = fmaxf(mx1, __shfl_xor_sync(0xffffffffu, mx1, 1));
            mx1 = fmaxf(mx1, __shfl_xor_sync(0xffffffffu, mx1, 2));

            float mn0 = fmaxf(m_i[2 * mb + 0], mx0);
            float mn1 = fmaxf(m_i[2 * mb + 1], mx1);
            float al0 = __expf(m_i[2 * mb + 0] - mn0);
            float al1 = __expf(m_i[2 * mb + 1] - mn1);
            m_i[2 * mb + 0] = mn0;
            m_i[2 * mb + 1] = mn1;

            float s0 = 0.f, s1 = 0.f;
            int rbase  = (r0w + mb * 16 + g) * FSP;
            int rbase8 = (r0w + mb * 16 + g + 8) * FSP;
            #pragma unroll
            for (int nb = 0; nb < 8; nb++) {
                float p0 = __expf(sacc[mb][nb].x - mn0);
                float p1 = __expf(sacc[mb][nb].y - mn0);
                float p2 = __expf(sacc[mb][nb].z - mn1);
                float p3 = __expf(sacc[mb][nb].w - mn1);
                s0 += p0 + p1; s1 += p2 + p3;
                int cc = nb * 8 + 2 * t;
                *(half2*)&Ps[rbase + cc]  = __floats2half2_rn(p0, p1);
                *(half2*)&Ps[rbase8 + cc] = __floats2half2_rn(p2, p3);
            }
            s0 += __shfl_xor_sync(0xffffffffu, s0, 1);
            s0 += __shfl_xor_sync(0xffffffffu, s0, 2);
            s1 += __shfl_xor_sync(0xffffffffu, s1, 1);
            s1 += __shfl_xor_sync(0xffffffffu, s1, 2);
            l_i[2 * mb + 0] = l_i[2 * mb + 0] * al0 + s0;
            l_i[2 * mb + 1] = l_i[2 * mb + 1] * al1 + s1;

            #pragma unroll
            for (int nb = 0; nb < 8; nb++) {
                oacc[mb][nb].x *= al0; oacc[mb][nb].y *= al0;
                oacc[mb][nb].z *= al1; oacc[mb][nb].w *= al1;
            }
        }
        __syncwarp();

        #pragma unroll
        for (int ks = 0; ks < 4; ks++) {
            unsigned pf[2][4];
            #pragma unroll
            for (int mb = 0; mb < 2; mb++)
                ldsm4(pf[mb][0], pf[mb][1], pf[mb][2], pf[mb][3],
                      &Ps[(r0w + 16 * mb + arow) * FSP + ks * 16 + acol]);
            unsigned vf[8][2];
            #pragma unroll
            for (int jj = 0; jj < 4; jj++)
                ldsm4t(vf[2 * jj][0], vf[2 * jj][1], vf[2 * jj + 1][0], vf[2 * jj + 1][1],
                       &Vs[(ks * 16 + vrow) * FSP + 16 * jj + vcol]);
            #pragma unroll
            for (int mb = 0; mb < 2; mb++)
                #pragma unroll
                for (int nb = 0; nb < 8; nb++)
                    mma_f16(oacc[mb][nb], pf[mb][0], pf[mb][1], pf[mb][2], pf[mb][3],
                            vf[nb][0], vf[nb][1]);
        }
    }

    #pragma unroll
    for (int mb = 0; mb < 2; mb++) {
        float inv0 = 1.f / l_i[2 * mb + 0];
        float inv1 = 1.f / l_i[2 * mb + 1];
        int row0 = qt0 + r0w + mb * 16 + g;
        int row1 = row0 + 8;
        #pragma unroll
        for (int nb = 0; nb < 8; nb++) {
            int cc = nb * 8 + 2 * t;
            *(half2*)(o + obase + (size_t)row0 * D_ + cc) =
                __floats2half2_rn(oacc[mb][nb].x * inv0, oacc[mb][nb].y * inv0);
            *(half2*)(o + obase + (size_t)row1 * D_ + cc) =
                __floats2half2_rn(oacc[mb][nb].z * inv1, oacc[mb][nb].w * inv1);
        }
    }
}

// ---------------- launch ----------------
extern "C" void kernel_launch(void* const* d_in, const int* in_sizes, int n_in,
                              void* d_out, int out_size)
{
    const float* x    = (const float*)d_in[0];
    const float* ln1g = (const float*)d_in[1];
    const float* ln1b = (const float*)d_in[2];
    const float* ln2g = (const float*)d_in[3];
    const float* ln2b = (const float*)d_in[4];
    const float* wq   = (const float*)d_in[5];
    const float* bq   = (const float*)d_in[6];
    const float* wk   = (const float*)d_in[7];
    const float* bk   = (const float*)d_in[8];
    const float* wv   = (const float*)d_in[9];
    const float* bv   = (const float*)d_in[10];
    const float* wo   = (const float*)d_in[11];
    const float* bo   = (const float*)d_in[12];
    const float* w1   = (const float*)d_in[13];
    const float* b1   = (const float*)d_in[14];
    const float* w2   = (const float*)d_in[15];
    const float* b2   = (const float*)d_in[16];
    float* out = (float*)d_out;

    void* p;
    cudaGetSymbolAddress(&p, g_hh);   __half* h    = (__half*)p;
    cudaGetSymbolAddress(&p, g_qkv);  __half* qkv  = (__half*)p;
    cudaGetSymbolAddress(&p, g_ah);   __half* att  = (__half*)p;
    cudaGetSymbolAddress(&p, g_fh);   __half* ff   = (__half*)p;
    cudaGetSymbolAddress(&p, g_x2);   float*  x2   = (float*)p;
    cudaGetSymbolAddress(&p, g_wh);   __half* wh   = (__half*)p;
    cudaGetSymbolAddress(&p, g_bqkv); float*  bqkv = (float*)p;

    const size_t MB1 = 1024 * 1024;
    __half* hwqkv = wh;
    __half* hwo   = wh + 3 * MB1;
    __half* hw1   = wh + 4 * MB1;
    __half* hw2   = wh + 8 * MB1;

    cudaFuncSetAttribute(flash_h, cudaFuncAttributeMaxDynamicSharedMemorySize, FLASH_SMEM);
    cudaFuncSetAttribute(hgemm<8, false, false, true >, cudaFuncAttributeMaxDynamicSharedMemorySize, GSMEM8);
    cudaFuncSetAttribute(hgemm<4, true,  false, true >, cudaFuncAttributeMaxDynamicSharedMemorySize, GSMEM4);
    cudaFuncSetAttribute(hgemm<4, false, true,  false>, cudaFuncAttributeMaxDynamicSharedMemorySize, GSMEM4);

    w2h_all<<<(12 * SEG + 255) / 256, 256>>>(wq, wk, wv, wo, w1, w2, wh);
    bpack_k<<<(D_ + 255) / 256, 256>>>(bq, bk, bv, bqkv);

    dim3 gQKV(QKVN / 128, NT / 128);   // (24, 64) = 1536 CTAs, NBJ=8
    dim3 gD64(D_ / 64, NT / 128);      // (16, 64) = 1024 CTAs, NBJ=4
    dim3 gF(FF_ / 64, NT / 128);       // (64, 64) = 4096 CTAs, NBJ=4

    ln_k<<<NT, 256>>>(x, ln1g, ln1b, h);
    hgemm<8, false, false, true ><<<gQKV, 128, GSMEM8>>>(h, hwqkv, bqkv, nullptr, nullptr, qkv, NT, QKVN, D_);
    flash_h<<<dim3(T_ / 128, B_ * H_), 128, FLASH_SMEM>>>(qkv, att);
    hgemm<4, false, true,  false><<<gD64, 128, GSMEM4>>>(att, hwo, bo, x, x2, nullptr, NT, D_, D_);
    ln_k<<<NT, 256>>>(x2, ln2g, ln2b, h);
    hgemm<4, true,  false, true ><<<gF, 128, GSMEM4>>>(h, hw1, b1, nullptr, nullptr, ff, NT, FF_, D_);
    hgemm<4, false, true,  false><<<gD64, 128, GSMEM4>>>(ff, hw2, b2, x2, out, nullptr, NT, D_, FF_);
}

// round 17
// speedup vs baseline: 1.0552x; 1.0058x over previous
#include <cuda_runtime.h>
#include <cuda_fp16.h>
#include <math.h>
#include <stdint.h>

#define B_  4
#define T_  2048
#define D_  1024
#define H_  16
#define DH_ 64
#define FF_ 4096
#define NT  (B_*T_)   // 8192
#define QKVN 3072

// ---------------- scratch ----------------
__device__ __half g_hh  [(size_t)NT*D_];
__device__ __half g_qkv [(size_t)NT*QKVN];
__device__ __half g_ah  [(size_t)NT*D_];
__device__ __half g_fh  [(size_t)NT*FF_];
__device__ float  g_x2  [(size_t)NT*D_];
__device__ __half g_wh  [(size_t)12*1024*1024];
__device__ float  g_bqkv[QKVN];

#define SEG (262144)
#define W2H_BLOCKS 12288          // 12*SEG/256
#define LN_BLOCKS  NT             // 8192
#define PRO_BLOCKS (W2H_BLOCKS + LN_BLOCKS + 4)

// ---------------- fused prologue: weights->fp16 + bias pack + LN1 ----------------
__global__ void __launch_bounds__(256) prolog_k(const float* __restrict__ wq,
                                                const float* __restrict__ wk,
                                                const float* __restrict__ wv,
                                                const float* __restrict__ wo,
                                                const float* __restrict__ w1,
                                                const float* __restrict__ w2,
                                                __half* __restrict__ wdst,
                                                const float* __restrict__ bq,
                                                const float* __restrict__ bk,
                                                const float* __restrict__ bv,
                                                float* __restrict__ bqkv,
                                                const float* __restrict__ x,
                                                const float* __restrict__ ln1g,
                                                const float* __restrict__ ln1b,
                                                __half* __restrict__ hout)
{
    __shared__ float red[2][8];
    int blk = blockIdx.x;
    int tid = threadIdx.x;

    if (blk < W2H_BLOCKS) {
        // ---- weight conversion ----
        int i = blk * 256 + tid;
        const float* src;
        int s;
        if      (i <  1 * SEG) { src = wq; s = i; }
        else if (i <  2 * SEG) { src = wk; s = i - 1 * SEG; }
        else if (i <  3 * SEG) { src = wv; s = i - 2 * SEG; }
        else if (i <  4 * SEG) { src = wo; s = i - 3 * SEG; }
        else if (i <  8 * SEG) { src = w1; s = i - 4 * SEG; }
        else                   { src = w2; s = i - 8 * SEG; }
        float4 v = ((const float4*)src)[s];
        __half* d = wdst + (size_t)i * 4;
        *(half2*)(d)     = __floats2half2_rn(v.x, v.y);
        *(half2*)(d + 2) = __floats2half2_rn(v.z, v.w);
        return;
    }
    if (blk < W2H_BLOCKS + LN_BLOCKS) {
        // ---- LayerNorm1 ----
        int row = blk - W2H_BLOCKS;
        const float* xr = x + (size_t)row * D_;
        int c = tid * 4;
        float4 xv = *(const float4*)(xr + c);
        float s  = xv.x + xv.y + xv.z + xv.w;
        float ss = xv.x*xv.x + xv.y*xv.y + xv.z*xv.z + xv.w*xv.w;
        #pragma unroll
        for (int o = 16; o > 0; o >>= 1) {
            s  += __shfl_down_sync(0xffffffffu, s,  o);
            ss += __shfl_down_sync(0xffffffffu, ss, o);
        }
        if ((tid & 31) == 0) { red[0][tid >> 5] = s; red[1][tid >> 5] = ss; }
        __syncthreads();
        if (tid < 32) {
            s  = (tid < 8) ? red[0][tid] : 0.f;
            ss = (tid < 8) ? red[1][tid] : 0.f;
            #pragma unroll
            for (int o = 4; o > 0; o >>= 1) {
                s  += __shfl_down_sync(0xffffffffu, s,  o);
                ss += __shfl_down_sync(0xffffffffu, ss, o);
            }
            if (tid == 0) { red[0][0] = s; red[1][0] = ss; }
        }
        __syncthreads();
        float mean = red[0][0] * (1.f / D_);
        float var  = red[1][0] * (1.f / D_) - mean * mean;
        float rstd = rsqrtf(var + 1e-5f);
        float4 gv = *(const float4*)(ln1g + c);
        float4 bv = *(const float4*)(ln1b + c);
        float o0 = (xv.x - mean) * rstd * gv.x + bv.x;
        float o1 = (xv.y - mean) * rstd * gv.y + bv.y;
        float o2 = (xv.z - mean) * rstd * gv.z + bv.z;
        float o3 = (xv.w - mean) * rstd * gv.w + bv.w;
        *(half2*)(hout + (size_t)row * D_ + c)     = __floats2half2_rn(o0, o1);
        *(half2*)(hout + (size_t)row * D_ + c + 2) = __floats2half2_rn(o2, o3);
        return;
    }
    // ---- bias pack ----
    {
        int i = (blk - W2H_BLOCKS - LN_BLOCKS) * 256 + tid;
        if (i < D_) {
            bqkv[i] = bq[i];
            bqkv[i + D_] = bk[i];
            bqkv[i + 2 * D_] = bv[i];
        }
    }
}

// ---------------- LayerNorm (standalone, for LN2) ----------------
__global__ void __launch_bounds__(256) ln_k(const float* __restrict__ x,
                                            const float* __restrict__ g,
                                            const float* __restrict__ b,
                                            __half* __restrict__ out)
{
    __shared__ float red[2][8];
    int row = blockIdx.x;
    int tid = threadIdx.x;
    const float* xr = x + (size_t)row * D_;
    int c = tid * 4;
    float4 xv = *(const float4*)(xr + c);
    float s  = xv.x + xv.y + xv.z + xv.w;
    float ss = xv.x*xv.x + xv.y*xv.y + xv.z*xv.z + xv.w*xv.w;
    #pragma unroll
    for (int o = 16; o > 0; o >>= 1) {
        s  += __shfl_down_sync(0xffffffffu, s,  o);
        ss += __shfl_down_sync(0xffffffffu, ss, o);
    }
    if ((tid & 31) == 0) { red[0][tid >> 5] = s; red[1][tid >> 5] = ss; }
    __syncthreads();
    if (tid < 32) {
        s  = (tid < 8) ? red[0][tid] : 0.f;
        ss = (tid < 8) ? red[1][tid] : 0.f;
        #pragma unroll
        for (int o = 4; o > 0; o >>= 1) {
            s  += __shfl_down_sync(0xffffffffu, s,  o);
            ss += __shfl_down_sync(0xffffffffu, ss, o);
        }
        if (tid == 0) { red[0][0] = s; red[1][0] = ss; }
    }
    __syncthreads();
    float mean = red[0][0] * (1.f / D_);
    float var  = red[1][0] * (1.f / D_) - mean * mean;
    float rstd = rsqrtf(var + 1e-5f);
    float4 gv = *(const float4*)(g + c);
    float4 bv = *(const float4*)(b + c);
    float o0 = (xv.x - mean) * rstd * gv.x + bv.x;
    float o1 = (xv.y - mean) * rstd * gv.y + bv.y;
    float o2 = (xv.z - mean) * rstd * gv.z + bv.z;
    float o3 = (xv.w - mean) * rstd * gv.w + bv.w;
    *(half2*)(out + (size_t)row * D_ + c)     = __floats2half2_rn(o0, o1);
    *(half2*)(out + (size_t)row * D_ + c + 2) = __floats2half2_rn(o2, o3);
}

// ---------------- mma / ldmatrix / cp.async helpers ----------------
__device__ __forceinline__ void mma_f16(float4& c,
                                        unsigned a0, unsigned a1, unsigned a2, unsigned a3,
                                        unsigned b0, unsigned b1)
{
    asm volatile("mma.sync.aligned.m16n8k16.row.col.f32.f16.f16.f32 "
                 "{%0,%1,%2,%3}, {%4,%5,%6,%7}, {%8,%9}, {%0,%1,%2,%3};"
                 : "+f"(c.x), "+f"(c.y), "+f"(c.z), "+f"(c.w)
                 : "r"(a0), "r"(a1), "r"(a2), "r"(a3), "r"(b0), "r"(b1));
}
__device__ __forceinline__ void ldsm4(unsigned& r0, unsigned& r1, unsigned& r2, unsigned& r3,
                                      const __half* p)
{
    uint32_t a = (uint32_t)__cvta_generic_to_shared(p);
    asm volatile("ldmatrix.sync.aligned.m8n8.x4.shared.b16 {%0,%1,%2,%3}, [%4];"
                 : "=r"(r0), "=r"(r1), "=r"(r2), "=r"(r3) : "r"(a));
}
__device__ __forceinline__ void ldsm4t(unsigned& r0, unsigned& r1, unsigned& r2, unsigned& r3,
                                       const __half* p)
{
    uint32_t a = (uint32_t)__cvta_generic_to_shared(p);
    asm volatile("ldmatrix.sync.aligned.m8n8.x4.trans.shared.b16 {%0,%1,%2,%3}, [%4];"
                 : "=r"(r0), "=r"(r1), "=r"(r2), "=r"(r3) : "r"(a));
}
__device__ __forceinline__ void cp16(const __half* smem_dst, const __half* gptr) {
    uint32_t a = (uint32_t)__cvta_generic_to_shared(smem_dst);
    asm volatile("cp.async.cg.shared.global [%0], [%1], 16;\n" :: "r"(a), "l"(gptr));
}
__device__ __forceinline__ void cp_commit() { asm volatile("cp.async.commit_group;\n"); }
template<int N>
__device__ __forceinline__ void cp_wait() { asm volatile("cp.async.wait_group %0;\n" :: "n"(N)); }

// ---------------- fp16 GEMM (templated N-tile; NBJ=8 or 4) ----------------
#define SPADH 40
template<int NBJ, bool GELU, bool RES, bool HOUT>
__global__ void __launch_bounds__(128) hgemm(const __half* __restrict__ A,
                                             const __half* __restrict__ W,
                                             const float* __restrict__ bias,
                                             const float* __restrict__ res,
                                             float* __restrict__ Cf,
                                             __half* __restrict__ Ch,
                                             int M, int N, int K)
{
    constexpr int NROWS = NBJ * 16;
    constexpr int STGH  = (128 + NROWS) * SPADH;

    extern __shared__ __half smg[];

    int tid  = threadIdx.x;
    int warp = tid >> 5;
    int lane = tid & 31;
    int g = lane >> 2;
    int t = lane & 3;
    int wm = (warp >> 1) * 64;
    int wn = (warp & 1) * (NBJ * 8);

    int m0 = blockIdx.y * 128;
    int n0 = blockIdx.x * NROWS;

    int lrow[4], lcb[4];
    #pragma unroll
    for (int u = 0; u < 4; u++) {
        int lin = tid + u * 128;
        lrow[u] = lin >> 2;
        lcb[u]  = (lin & 3) * 8;
    }

    int arow = (lane & 15);
    int acol = 8 * (lane >> 4);
    int brow = (lane & 7) + ((lane >> 4) << 3);
    int bcol = 8 * ((lane >> 3) & 1);

    float4 acc[4][NBJ];
    #pragma unroll
    for (int i = 0; i < 4; i++)
        #pragma unroll
        for (int j = 0; j < NBJ; j++) acc[i][j] = make_float4(0.f, 0.f, 0.f, 0.f);

    #pragma unroll
    for (int st = 0; st < 2; st++) {
        __half* As = smg + st * STGH;
        __half* Bs = As + 128 * SPADH;
        #pragma unroll
        for (int u = 0; u < 4; u++)
            cp16(&As[lrow[u] * SPADH + lcb[u]],
                 A + (size_t)(m0 + lrow[u]) * K + st * 32 + lcb[u]);
        #pragma unroll
        for (int u = 0; u < NBJ / 2; u++) {
            int lin = tid + u * 128;
            int row = lin >> 2;
            int cb  = (lin & 3) * 8;
            cp16(&Bs[row * SPADH + cb],
                 W + (size_t)(n0 + row) * K + st * 32 + cb);
        }
        cp_commit();
    }

    int niter = K >> 5;
    int sidx = 0;
    for (int kt = 0; kt < niter; kt++) {
        cp_wait<1>();
        __syncthreads();
        const __half* Ab = smg + sidx * STGH;
        const __half* Bb = Ab + 128 * SPADH;

        #pragma unroll
        for (int kk = 0; kk < 32; kk += 16) {
            unsigned af[4][4];
            #pragma unroll
            for (int i = 0; i < 4; i++)
                ldsm4(af[i][0], af[i][1], af[i][2], af[i][3],
                      &Ab[(wm + 16 * i + arow) * SPADH + kk + acol]);
            unsigned bf[NBJ][2];
            #pragma unroll
            for (int jj = 0; jj < NBJ / 2; jj++)
                ldsm4(bf[2 * jj][0], bf[2 * jj][1], bf[2 * jj + 1][0], bf[2 * jj + 1][1],
                      &Bb[(wn + 16 * jj + brow) * SPADH + kk + bcol]);
            #pragma unroll
            for (int i = 0; i < 4; i++)
                #pragma unroll
                for (int j = 0; j < NBJ; j++)
                    mma_f16(acc[i][j], af[i][0], af[i][1], af[i][2], af[i][3],
                            bf[j][0], bf[j][1]);
        }

        int j2 = kt + 2;
        if (j2 < niter) {
            int s2 = sidx + 2; if (s2 >= 3) s2 -= 3;
            __half* As = smg + s2 * STGH;
            __half* Bs = As + 128 * SPADH;
            int k0n = j2 * 32;
            #pragma unroll
            for (int u = 0; u < 4; u++)
                cp16(&As[lrow[u] * SPADH + lcb[u]],
                     A + (size_t)(m0 + lrow[u]) * K + k0n + lcb[u]);
            #pragma unroll
            for (int u = 0; u < NBJ / 2; u++) {
                int lin = tid + u * 128;
                int row = lin >> 2;
                int cb  = (lin & 3) * 8;
                cp16(&Bs[row * SPADH + cb],
                     W + (size_t)(n0 + row) * K + k0n + cb);
            }
        }
        cp_commit();
        sidx++; if (sidx == 3) sidx = 0;
    }

    #pragma unroll
    for (int i = 0; i < 4; i++) {
        int r0 = m0 + wm + 16 * i + g;
        int r1 = r0 + 8;
        #pragma unroll
        for (int j = 0; j < NBJ; j++) {
            int col = n0 + wn + 8 * j + 2 * t;
            float b0 = bias[col], b1 = bias[col + 1];
            float v0 = acc[i][j].x + b0;
            float v1 = acc[i][j].y + b1;
            float v2 = acc[i][j].z + b0;
            float v3 = acc[i][j].w + b1;
            if (RES) {
                const float* rp0 = res + (size_t)r0 * N + col;
                const float* rp1 = res + (size_t)r1 * N + col;
                v0 += rp0[0]; v1 += rp0[1]; v2 += rp1[0]; v3 += rp1[1];
            }
            if (GELU) {
                v0 *= normcdff(v0); v1 *= normcdff(v1);
                v2 *= normcdff(v2); v3 *= normcdff(v3);
            }
            if (HOUT) {
                *(half2*)(Ch + (size_t)r0 * N + col) = __floats2half2_rn(v0, v1);
                *(half2*)(Ch + (size_t)r1 * N + col) = __floats2half2_rn(v2, v3);
            } else {
                *(float2*)(Cf + (size_t)r0 * N + col) = make_float2(v0, v1);
                *(float2*)(Cf + (size_t)r1 * N + col) = make_float2(v2, v3);
            }
        }
    }
}

#define GSMEM8 (3 * (128 + 128) * SPADH * (int)sizeof(__half))   // 61,440 B
#define GSMEM4 (3 * (128 + 64)  * SPADH * (int)sizeof(__half))   // 46,080 B

// ---------------- fp16 flash attention (R12 exact) ----------------
#define FSP 72
#define FLASH_SMEM ((128 + 64 + 64 + 128) * FSP * (int)sizeof(__half))
__global__ void __launch_bounds__(128) flash_h(const __half* __restrict__ qkv,
                                               __half* __restrict__ o)
{
    extern __shared__ __half smh[];
    __half* Qs = smh;
    __half* Ks = Qs + 128 * FSP;
    __half* Vs = Ks + 64 * FSP;
    __half* Ps = Vs + 64 * FSP;

    int tid  = threadIdx.x;
    int warp = tid >> 5;
    int lane = tid & 31;
    int g = lane >> 2;
    int t = lane & 3;

    int bh = blockIdx.y;
    int b  = bh >> 4;
    int h  = bh & 15;
    int qt0 = blockIdx.x * 128;
    size_t qbase = ((size_t)b * T_) * QKVN + (size_t)h * DH_;
    size_t kbase = qbase + D_;
    size_t vbase = qbase + 2 * D_;
    size_t obase = ((size_t)b * T_) * D_ + (size_t)h * DH_;

    int arow = (lane & 15);
    int acol = 8 * (lane >> 4);
    int brow = (lane & 7) + ((lane >> 4) << 3);
    int bcol = 8 * ((lane >> 3) & 1);
    int vrow = (lane & 7) + (((lane >> 3) & 1) << 3);
    int vcol = 8 * (lane >> 4);

    {
        half2 sc = __float2half2_rn(0.125f);
        #pragma unroll
        for (int it = 0; it < 8; it++) {
            int lin = tid + it * 128;
            int row = lin >> 3;
            int cb  = (lin & 7) * 8;
            uint4 u = *(const uint4*)(qkv + qbase + (size_t)(qt0 + row) * QKVN + cb);
            half2* hp = (half2*)&u;
            hp[0] = __hmul2(hp[0], sc); hp[1] = __hmul2(hp[1], sc);
            hp[2] = __hmul2(hp[2], sc); hp[3] = __hmul2(hp[3], sc);
            *(uint4*)&Qs[row * FSP + cb] = u;
        }
    }
    __syncthreads();

    int r0w = warp * 32;

    unsigned qf[2][4][4];
    #pragma unroll
    for (int mb = 0; mb < 2; mb++)
        #pragma unroll
        for (int ks = 0; ks < 4; ks++)
            ldsm4(qf[mb][ks][0], qf[mb][ks][1], qf[mb][ks][2], qf[mb][ks][3],
                  &Qs[(r0w + 16 * mb + arow) * FSP + ks * 16 + acol]);

    float m_i[4] = {-1e30f, -1e30f, -1e30f, -1e30f};
    float l_i[4] = {0.f, 0.f, 0.f, 0.f};
    float4 oacc[2][8];
    #pragma unroll
    for (int mb = 0; mb < 2; mb++)
        #pragma unroll
        for (int nb = 0; nb < 8; nb++) oacc[mb][nb] = make_float4(0.f, 0.f, 0.f, 0.f);

    for (int kt0 = 0; kt0 < T_; kt0 += 64) {
        __syncthreads();
        #pragma unroll
        for (int it = 0; it < 4; it++) {
            int lin = tid + it * 128;
            int row = lin >> 3;
            int cb  = (lin & 7) * 8;
            *(uint4*)&Ks[row * FSP + cb] =
                *(const uint4*)(qkv + kbase + (size_t)(kt0 + row) * QKVN + cb);
            *(uint4*)&Vs[row * FSP + cb] =
                *(const uint4*)(qkv + vbase + (size_t)(kt0 + row) * QKVN + cb);
        }
        __syncthreads();

        float4 sacc[2][8];
        #pragma unroll
        for (int mb = 0; mb < 2; mb++)
            #pragma unroll
            for (int nb = 0; nb < 8; nb++) sacc[mb][nb] = make_float4(0.f, 0.f, 0.f, 0.f);
        #pragma unroll
        for (int ks = 0; ks < 4; ks++) {
            unsigned bb[8][2];
            #pragma unroll
            for (int jj = 0; jj < 4; jj++)
                ldsm4(bb[2 * jj][0], bb[2 * jj][1], bb[2 * jj + 1][0], bb[2 * jj + 1][1],
                      &Ks[(16 * jj + brow) * FSP + ks * 16 + bcol]);
            #pragma unroll
            for (int mb = 0; mb < 2; mb++)
                #pragma unroll
                for (int nb = 0; nb < 8; nb++)
                    mma_f16(sacc[mb][nb], qf[mb][ks][0], qf[mb][ks][1],
                            qf[mb][ks][2], qf[mb][ks][3], bb[nb][0], bb[nb][1]);
        }

        #pragma unroll
        for (int mb = 0; mb < 2; mb++) {
            float mx0 = -1e30f, mx1 = -1e30f;
            #pragma unroll
            for (int nb = 0; nb < 8; nb++) {
                mx0 = fmaxf(mx0, fmaxf(sacc[mb][nb].x, sacc[mb][nb].y));
                mx1 = fmaxf(mx1, fmaxf(sacc[mb][nb].z, sacc[mb][nb].w));
            }
            mx0 = fmaxf(mx0, __shfl_xor_sync(0xffffffffu, mx0, 1));
            mx0 = fmaxf(mx0, __shfl_xor_sync(0xffffffffu, mx0, 2));
            mx1 = fmaxf(mx1, __shfl_xor_sync(0xffffffffu, mx1, 1));
            mx1 = fmaxf(mx1, __shfl_xor_sync(0xffffffffu, mx1, 2));

            float mn0 = fmaxf(m_i[2 * mb + 0], mx0);
            float mn1 = fmaxf(m_i[2 * mb + 1], mx1);
            float al0 = __expf(m_i[2 * mb + 0] - mn0);
            float al1 = __expf(m_i[2 * mb + 1] - mn1);
            m_i[2 * mb + 0] = mn0;
            m_i[2 * mb + 1] = mn1;

            float s0 = 0.f, s1 = 0.f;
            int rbase  = (r0w + mb * 16 + g) * FSP;
            int rbase8 = (r0w + mb * 16 + g + 8) * FSP;
            #pragma unroll
            for (int nb = 0; nb < 8; nb++) {
                float p0 = __expf(sacc[mb][nb].x - mn0);
                float p1 = __expf(sacc[mb][nb].y - mn0);
                float p2 = __expf(sacc[mb][nb].z - mn1);
                float p3 = __expf(sacc[mb][nb].w - mn1);
                s0 += p0 + p1; s1 += p2 + p3;
                int cc = nb * 8 + 2 * t;
                *(half2*)&Ps[rbase + cc]  = __floats2half2_rn(p0, p1);
                *(half2*)&Ps[rbase8 + cc] = __floats2half2_rn(p2, p3);
            }
            s0 += __shfl_xor_sync(0xffffffffu, s0, 1);
            s0 += __shfl_xor_sync(0xffffffffu, s0, 2);
            s1 += __shfl_xor_sync(0xffffffffu, s1, 1);
            s1 += __shfl_xor_sync(0xffffffffu, s1, 2);
            l_i[2 * mb + 0] = l_i[2 * mb + 0] * al0 + s0;
            l_i[2 * mb + 1] = l_i[2 * mb + 1] * al1 + s1;

            #pragma unroll
            for (int nb = 0; nb < 8; nb++) {
                oacc[mb][nb].x *= al0; oacc[mb][nb].y *= al0;
                oacc[mb][nb].z *= al1; oacc[mb][nb].w *= al1;
            }
        }
        __syncwarp();

        #pragma unroll
        for (int ks = 0; ks < 4; ks++) {
            unsigned pf[2][4];
            #pragma unroll
            for (int mb = 0; mb < 2; mb++)
                ldsm4(pf[mb][0], pf[mb][1], pf[mb][2], pf[mb][3],
                      &Ps[(r0w + 16 * mb + arow) * FSP + ks * 16 + acol]);
            unsigned vf[8][2];
            #pragma unroll
            for (int jj = 0; jj < 4; jj++)
                ldsm4t(vf[2 * jj][0], vf[2 * jj][1], vf[2 * jj + 1][0], vf[2 * jj + 1][1],
                       &Vs[(ks * 16 + vrow) * FSP + 16 * jj + vcol]);
            #pragma unroll
            for (int mb = 0; mb < 2; mb++)
                #pragma unroll
                for (int nb = 0; nb < 8; nb++)
                    mma_f16(oacc[mb][nb], pf[mb][0], pf[mb][1], pf[mb][2], pf[mb][3],
                            vf[nb][0], vf[nb][1]);
        }
    }

    #pragma unroll
    for (int mb = 0; mb < 2; mb++) {
        float inv0 = 1.f / l_i[2 * mb + 0];
        float inv1 = 1.f / l_i[2 * mb + 1];
        int row0 = qt0 + r0w + mb * 16 + g;
        int row1 = row0 + 8;
        #pragma unroll
        for (int nb = 0; nb < 8; nb++) {
            int cc = nb * 8 + 2 * t;
            *(half2*)(o + obase + (size_t)row0 * D_ + cc) =
                __floats2half2_rn(oacc[mb][nb].x * inv0, oacc[mb][nb].y * inv0);
            *(half2*)(o + obase + (size_t)row1 * D_ + cc) =
                __floats2half2_rn(oacc[mb][nb].z * inv1, oacc[mb][nb].w * inv1);
        }
    }
}

// ---------------- launch ----------------
extern "C" void kernel_launch(void* const* d_in, const int* in_sizes, int n_in,
                              void* d_out, int out_size)
{
    const float* x    = (const float*)d_in[0];
    const float* ln1g = (const float*)d_in[1];
    const float* ln1b = (const float*)d_in[2];
    const float* ln2g = (const float*)d_in[3];
    const float* ln2b = (const float*)d_in[4];
    const float* wq   = (const float*)d_in[5];
    const float* bq   = (const float*)d_in[6];
    const float* wk   = (const float*)d_in[7];
    const float* bk   = (const float*)d_in[8];
    const float* wv   = (const float*)d_in[9];
    const float* bv   = (const float*)d_in[10];
    const float* wo   = (const float*)d_in[11];
    const float* bo   = (const float*)d_in[12];
    const float* w1   = (const float*)d_in[13];
    const float* b1   = (const float*)d_in[14];
    const float* w2   = (const float*)d_in[15];
    const float* b2   = (const float*)d_in[16];
    float* out = (float*)d_out;

    void* p;
    cudaGetSymbolAddress(&p, g_hh);   __half* h    = (__half*)p;
    cudaGetSymbolAddress(&p, g_qkv);  __half* qkv  = (__half*)p;
    cudaGetSymbolAddress(&p, g_ah);   __half* att  = (__half*)p;
    cudaGetSymbolAddress(&p, g_fh);   __half* ff   = (__half*)p;
    cudaGetSymbolAddress(&p, g_x2);   float*  x2   = (float*)p;
    cudaGetSymbolAddress(&p, g_wh);   __half* wh   = (__half*)p;
    cudaGetSymbolAddress(&p, g_bqkv); float*  bqkv = (float*)p;

    const size_t MB1 = 1024 * 1024;
    __half* hwqkv = wh;
    __half* hwo   = wh + 3 * MB1;
    __half* hw1   = wh + 4 * MB1;
    __half* hw2   = wh + 8 * MB1;

    cudaFuncSetAttribute(flash_h, cudaFuncAttributeMaxDynamicSharedMemorySize, FLASH_SMEM);
    cudaFuncSetAttribute(hgemm<8, false, false, true >, cudaFuncAttributeMaxDynamicSharedMemorySize, GSMEM8);
    cudaFuncSetAttribute(hgemm<4, true,  false, true >, cudaFuncAttributeMaxDynamicSharedMemorySize, GSMEM4);
    cudaFuncSetAttribute(hgemm<4, false, true,  false>, cudaFuncAttributeMaxDynamicSharedMemorySize, GSMEM4);

    // fused prologue: weight conversion + LN1 + bias pack in one launch
    prolog_k<<<PRO_BLOCKS, 256>>>(wq, wk, wv, wo, w1, w2, wh,
                                  bq, bk, bv, bqkv,
                                  x, ln1g, ln1b, h);

    dim3 gQKV(QKVN / 128, NT / 128);   // (24, 64) = 1536 CTAs, NBJ=8
    dim3 gD64(D_ / 64, NT / 128);      // (16, 64) = 1024 CTAs, NBJ=4
    dim3 gF(FF_ / 64, NT / 128);       // (64, 64) = 4096 CTAs, NBJ=4

    hgemm<8, false, false, true ><<<gQKV, 128, GSMEM8>>>(h, hwqkv, bqkv, nullptr, nullptr, qkv, NT, QKVN, D_);
    flash_h<<<dim3(T_ / 128, B_ * H_), 128, FLASH_SMEM>>>(qkv, att);
    hgemm<4, false, true,  false><<<gD64, 128, GSMEM4>>>(att, hwo, bo, x, x2, nullptr, NT, D_, D_);
    ln_k<<<NT, 256>>>(x2, ln2g, ln2b, h);
    hgemm<4, true,  false, true ><<<gF, 128, GSMEM4>>>(h, hw1, b1, nullptr, nullptr, ff, NT, FF_, D_);
    hgemm<4, false, true,  false><<<gD64, 128, GSMEM4>>>(ff, hw2, b2, x2, out, nullptr, NT, D_, FF_);
}